// round 11
// baseline (speedup 1.0000x reference)
#include <cuda_runtime.h>
#include <cuda_bf16.h>
#include <math.h>
#include <stdint.h>

// Problem constants
#define NB   4
#define SEQ  2048
#define DH   1024
#define NH   16
#define HD   64
#define MROWS (NB*SEQ)          // 8192

#define GM MROWS
#define GN DH
#define GK DH

// ---------------- scratch (static device globals; no allocation) -------------
__device__ float g_xn[MROWS * DH];      // permuted cols
__device__ float g_q [MROWS * DH];      // permuted cols
__device__ float g_k [MROWS * DH];      // permuted cols
__device__ float g_v [MROWS * DH];      // TRANSPOSED: [NB][NH][HD][SEQ], y permuted
__device__ float g_z [MROWS * DH];      // permuted cols
__device__ float g_wt[4][DH * DH];      // tf32, permuted cols (q,k,v,o)
__device__ float g_bqkv[3 * DH];        // packed biases (logical order)

// ---------------------------- helpers -----------------------------------------
// per-8 column permutation: logical j -> position 2*(j&3) + (j>>2)
__device__ __forceinline__ int pi8(int j) { return ((j & 3) << 1) | (j >> 2); }

__device__ __forceinline__ float f_tf32(float x) {
    uint32_t r;
    asm("cvt.rna.tf32.f32 %0, %1;" : "=r"(r) : "f"(x));
    return __uint_as_float(r);
}

__device__ __forceinline__ void mma_tf32(float* c, const float* a, const float* b) {
    asm volatile(
        "mma.sync.aligned.m16n8k8.row.col.f32.tf32.tf32.f32 "
        "{%0,%1,%2,%3}, {%4,%5,%6,%7}, {%8,%9}, {%0,%1,%2,%3};\n"
        : "+f"(c[0]), "+f"(c[1]), "+f"(c[2]), "+f"(c[3])
        : "r"(__float_as_uint(a[0])), "r"(__float_as_uint(a[1])),
          "r"(__float_as_uint(a[2])), "r"(__float_as_uint(a[3])),
          "r"(__float_as_uint(b[0])), "r"(__float_as_uint(b[1])));
}

__device__ __forceinline__ void cp_async16(void* smem, const void* gmem) {
    uint32_t s = (uint32_t)__cvta_generic_to_shared(smem);
    asm volatile("cp.async.cg.shared.global [%0], [%1], 16;" :: "r"(s), "l"(gmem));
}
__device__ __forceinline__ void cp_commit() {
    asm volatile("cp.async.commit_group;");
}
template<int N>
__device__ __forceinline__ void cp_wait() {
    asm volatile("cp.async.wait_group %0;" :: "n"(N));
}

// ----------------- weight pre-round (tf32) + permute + bias pack ---------------
__global__ __launch_bounds__(256) void wcvt_kernel(
    const float* __restrict__ w0, const float* __restrict__ w1,
    const float* __restrict__ w2, const float* __restrict__ w3,
    float* __restrict__ dst)
{
    const float* srcs[4] = {w0, w1, w2, w3};
    const float* src = srcs[blockIdx.y];
    float* d = dst + (size_t)blockIdx.y * DH * DH;
    int i = (blockIdx.x * 256 + threadIdx.x) * 4;
    float4 v = *(const float4*)&src[i];
    int base = i & ~7;
    int j0 = i & 7;          // 0 or 4
    d[base + pi8(j0 + 0)] = f_tf32(v.x);
    d[base + pi8(j0 + 1)] = f_tf32(v.y);
    d[base + pi8(j0 + 2)] = f_tf32(v.z);
    d[base + pi8(j0 + 3)] = f_tf32(v.w);
}

__global__ __launch_bounds__(256) void bpack_kernel(
    const float* __restrict__ b0, const float* __restrict__ b1,
    const float* __restrict__ b2, float* __restrict__ dst)
{
    int i = blockIdx.x * 256 + threadIdx.x;
    dst[i]          = b0[i];
    dst[i + DH]     = b1[i];
    dst[i + 2 * DH] = b2[i];
}

// ---------------- LayerNorm (warp per row, tf32 + permuted out) ----------------
__global__ __launch_bounds__(256) void ln_kernel(
    const float* __restrict__ x, const float* __restrict__ gamma,
    const float* __restrict__ beta, float* __restrict__ xn)
{
    int warp = threadIdx.x >> 5, lane = threadIdx.x & 31;
    int row = blockIdx.x * 8 + warp;
    const float* xr = x + (size_t)row * DH;
    float* outr = xn + (size_t)row * DH;

    float4 v[8];
    float s = 0.f, sq = 0.f;
    #pragma unroll
    for (int j = 0; j < 8; j++) {
        v[j] = *(const float4*)&xr[(j * 32 + lane) * 4];
        s  += v[j].x + v[j].y + v[j].z + v[j].w;
        sq += v[j].x * v[j].x + v[j].y * v[j].y
            + v[j].z * v[j].z + v[j].w * v[j].w;
    }
    #pragma unroll
    for (int off = 16; off > 0; off >>= 1) {
        s  += __shfl_xor_sync(0xffffffffu, s,  off);
        sq += __shfl_xor_sync(0xffffffffu, sq, off);
    }
    float mu  = s * (1.0f / DH);
    float var = sq * (1.0f / DH) - mu * mu;
    float inv = rsqrtf(var + 1e-5f);

    #pragma unroll
    for (int j = 0; j < 8; j++) {
        int c = (j * 32 + lane) * 4;
        float4 g = *(const float4*)&gamma[c];
        float4 b = *(const float4*)&beta[c];
        int base = c & ~7;
        int j0 = c & 7;
        outr[base + pi8(j0 + 0)] = f_tf32((v[j].x - mu) * inv * g.x + b.x);
        outr[base + pi8(j0 + 1)] = f_tf32((v[j].y - mu) * inv * g.y + b.y);
        outr[base + pi8(j0 + 2)] = f_tf32((v[j].z - mu) * inv * g.z + b.z);
        outr[base + pi8(j0 + 3)] = f_tf32((v[j].w - mu) * inv * g.w + b.w);
    }
}

// ----------- GEMM core (tf32, cp.async 2-stage, ONE sync/iter) ----------------
#define SA 40
#define GTILE (128 * SA)
#define GEMM_SMEM (4 * GTILE * (int)sizeof(float))

struct GemmCore {
    float acc[4][4][4];
    int t, lane, wid, lr, lc, m_base, n_base;

    __device__ __forceinline__ void init(int tid) {
        t = tid; lane = t & 31; wid = t >> 5;
        lr = lane >> 2; lc = lane & 3;
        m_base = (wid & 1) * 64;
        n_base = (wid >> 1) * 32;
        #pragma unroll
        for (int i = 0; i < 4; i++)
            #pragma unroll
            for (int j = 0; j < 4; j++)
                #pragma unroll
                for (int e = 0; e < 4; e++) acc[i][j][e] = 0.f;
    }

    __device__ __forceinline__ void run(
        float* As, float* Bs,
        const float* __restrict__ A, const float* __restrict__ W, int m0)
    {
        // prologue: tile 0 into buf 0
        #pragma unroll
        for (int i = 0; i < 4; i++) {
            int e = t + i * 256;
            int row = e >> 3, c4 = (e & 7) * 4;
            cp_async16(&As[row * SA + c4], &A[(size_t)(m0 + row) * GK + c4]);
            cp_async16(&Bs[row * SA + c4], &W[(size_t)row * GK + c4]);
        }
        cp_commit();

        int buf = 0;
        for (int k0 = 0; k0 < GK; k0 += 32) {
            bool more = (k0 + 32 < GK);
            cp_wait<0>();      // tile i's group complete (only one outstanding)
            __syncthreads();   // visible to all; also: iter i-1 compute finished

            if (more) {
                float* Aw = &As[(buf ^ 1) * GTILE];
                float* Bw = &Bs[(buf ^ 1) * GTILE];
                #pragma unroll
                for (int i = 0; i < 4; i++) {
                    int e = t + i * 256;
                    int row = e >> 3, c4 = (e & 7) * 4;
                    cp_async16(&Aw[row * SA + c4],
                               &A[(size_t)(m0 + row) * GK + k0 + 32 + c4]);
                    cp_async16(&Bw[row * SA + c4],
                               &W[(size_t)row * GK + k0 + 32 + c4]);
                }
                cp_commit();
            }

            const float* Ab = &As[buf * GTILE];
            const float* Bb = &Bs[buf * GTILE];
            #pragma unroll
            for (int kk = 0; kk < 4; kk++) {
                int kb = kk * 8 + 2 * lc;
                float a[4][4], b[4][2];
                #pragma unroll
                for (int mf = 0; mf < 4; mf++) {
                    int row = m_base + mf * 16 + lr;
                    float2 lo = *(const float2*)&Ab[row * SA + kb];
                    float2 hi = *(const float2*)&Ab[(row + 8) * SA + kb];
                    a[mf][0] = lo.x; a[mf][1] = hi.x;
                    a[mf][2] = lo.y; a[mf][3] = hi.y;
                }
                #pragma unroll
                for (int nf = 0; nf < 4; nf++) {
                    int col = n_base + nf * 8 + lr;
                    float2 bb = *(const float2*)&Bb[col * SA + kb];
                    b[nf][0] = bb.x; b[nf][1] = bb.y;
                }
                #pragma unroll
                for (int mf = 0; mf < 4; mf++)
                    #pragma unroll
                    for (int nf = 0; nf < 4; nf++)
                        mma_tf32(acc[mf][nf], a[mf], b[nf]);
            }
            buf ^= 1;
        }
    }
};

// Fused QKV GEMM. Wp: [3072 x 1024] permuted-col. Writes q,k permuted-col;
// v transposed [NB][NH][HD][SEQ] with y permuted (for attention PV).
__global__ __launch_bounds__(256, 2) void gemm_qkv_kernel(
    const float* __restrict__ A, const float* __restrict__ Wp,
    const float* __restrict__ bp,
    float* __restrict__ q, float* __restrict__ k, float* __restrict__ v)
{
    extern __shared__ float gsm[];
    GemmCore core;
    core.init(threadIdx.x);

    int npack0 = blockIdx.x * 128;
    int m0 = blockIdx.y * 128;
    int mat = npack0 >> 10;               // 0=q 1=k 2=v
    int ncol0 = npack0 & 1023;

    core.run(gsm, gsm + 2 * GTILE, A, Wp + (size_t)npack0 * GK, m0);

    const float* bias = bp + npack0;
    int lr = core.lr, lc = core.lc;
    int p0 = pi8(2 * lc), p1 = pi8(2 * lc + 1);

    #pragma unroll
    for (int nf = 0; nf < 4; nf++) {
        int cb = core.n_base + nf * 8;
        float b0 = bias[cb + 2 * lc];
        float b1 = bias[cb + 2 * lc + 1];
        #pragma unroll
        for (int mf = 0; mf < 4; mf++) {
            int row = m0 + core.m_base + mf * 16 + lr;
            float v0 = f_tf32(core.acc[mf][nf][0] + b0);
            float v1 = f_tf32(core.acc[mf][nf][1] + b1);
            float v2 = f_tf32(core.acc[mf][nf][2] + b0);
            float v3 = f_tf32(core.acc[mf][nf][3] + b1);
            if (mat == 2) {
                int c0 = ncol0 + cb + 2 * lc;
                int yl = row & (SEQ - 1);
                int py = (yl & ~7) | pi8(yl & 7);
                size_t b_ = (size_t)(row >> 11) * DH;
                v[(b_ + c0)     * SEQ + py]     = v0;
                v[(b_ + c0 + 1) * SEQ + py]     = v1;
                v[(b_ + c0)     * SEQ + py + 8] = v2;
                v[(b_ + c0 + 1) * SEQ + py + 8] = v3;
            } else {
                float* C = (mat == 0) ? q : k;
                int colb = ncol0 + cb;
                C[(size_t)row * GN + colb + p0]       = v0;
                C[(size_t)row * GN + colb + p1]       = v1;
                C[(size_t)(row + 8) * GN + colb + p0] = v2;
                C[(size_t)(row + 8) * GN + colb + p1] = v3;
            }
        }
    }
}

// Output projection: A (z) permuted-col, W permuted-col, OUTPUT standard layout.
__global__ __launch_bounds__(256, 2) void gemm_o_kernel(
    const float* __restrict__ A, const float* __restrict__ W,
    const float* __restrict__ bias, float* __restrict__ C)
{
    extern __shared__ float gsm[];
    GemmCore core;
    core.init(threadIdx.x);
    int n0 = blockIdx.x * 128;
    int m0 = blockIdx.y * 128;
    core.run(gsm, gsm + 2 * GTILE, A, W + (size_t)n0 * GK, m0);

    int lr = core.lr, lc = core.lc;
    #pragma unroll
    for (int nf = 0; nf < 4; nf++) {
        int col = n0 + core.n_base + nf * 8 + 2 * lc;
        float b0 = bias[col], b1 = bias[col + 1];
        #pragma unroll
        for (int mf = 0; mf < 4; mf++) {
            int row = m0 + core.m_base + mf * 16 + lr;
            *(float2*)&C[(size_t)row * GN + col] =
                make_float2(core.acc[mf][nf][0] + b0, core.acc[mf][nf][1] + b1);
            *(float2*)&C[(size_t)(row + 8) * GN + col] =
                make_float2(core.acc[mf][nf][2] + b0, core.acc[mf][nf][3] + b1);
        }
    }
}

// ------ Flash Attention (tf32; Q in registers, double-buffered K/V) -----------
#define BQ  128
#define BKT 64
#define AST 72
#define KV_T (BKT * AST)
#define ATTN_SMEM ((4*KV_T + BQ*AST) * (int)sizeof(float))

__global__ __launch_bounds__(256, 2) void attn_kernel(
    const float* __restrict__ q, const float* __restrict__ k,
    const float* __restrict__ v, float* __restrict__ z)
{
    extern __shared__ float sm[];
    float* Ks = sm;                    // [2][64 y][AST] permuted d
    float* Vt = sm + 2 * KV_T;         // [2][64 d][AST] permuted y
    float* Ps = sm + 4 * KV_T;         // [128 r][AST]   permuted y (per-warp)

    int xc = (gridDim.x - 1) - blockIdx.x;   // heavy tiles first
    int h  = blockIdx.y;
    int n  = blockIdx.z;
    int x0 = xc * BQ;
    int t    = threadIdx.x;
    int lane = t & 31;
    int wid  = t >> 5;
    int lr = lane >> 2;
    int lc = lane & 3;
    int m_base = wid * 16;
    float* Pw = Ps + m_base * AST;
    int pp0 = pi8(2 * lc), pp1 = pi8(2 * lc + 1);

    const float* qb = q + ((size_t)n * SEQ) * DH + h * HD;
    const float* kb = k + ((size_t)n * SEQ) * DH + h * HD;
    const float* vtb = v + ((size_t)(n * NH + h) * HD) * SEQ;  // [64 d][2048 y]

    // prologue: K0/V0 via cp.async (one group per tile)
    #pragma unroll
    for (int i = 0; i < 4; i++) {
        int f = t + i * 256;
        int r = f >> 4, c4 = (f & 15) * 4;
        cp_async16(&Ks[r * AST + c4], &kb[(size_t)r * DH + c4]);
        cp_async16(&Vt[r * AST + c4], &vtb[(size_t)r * SEQ + c4]);
    }
    cp_commit();

    // Q fragments in registers for the whole kernel (1/8 scale folded in —
    // exact pow2, commutes bit-exactly through the fp32 mma chain)
    float qa[8][4];
    #pragma unroll
    for (int kk = 0; kk < 8; kk++) {
        float2 lo = *(const float2*)&qb[(size_t)(x0 + m_base + lr) * DH + kk * 8 + 2 * lc];
        float2 hi = *(const float2*)&qb[(size_t)(x0 + m_base + lr + 8) * DH + kk * 8 + 2 * lc];
        qa[kk][0] = lo.x * 0.125f; qa[kk][1] = hi.x * 0.125f;
        qa[kk][2] = lo.y * 0.125f; qa[kk][3] = hi.y * 0.125f;
    }

    float m_lo = -INFINITY, m_hi = -INFINITY, l_lo = 0.f, l_hi = 0.f;
    float o[8][4];
    #pragma unroll
    for (int nf = 0; nf < 8; nf++)
        #pragma unroll
        for (int e = 0; e < 4; e++) o[nf][e] = 0.f;

    int yend = x0 + BQ;
    int buf = 0;
    for (int y0 = 0; y0 < yend; y0 += BKT) {
        bool more = (y0 + BKT < yend);
        if (more) {
            // prefetch tile i+1 into buf^1 (its readers finished before the
            // previous end-of-iter barrier)
            float* Kw = &Ks[(buf ^ 1) * KV_T];
            float* Vw = &Vt[(buf ^ 1) * KV_T];
            #pragma unroll
            for (int i = 0; i < 4; i++) {
                int f = t + i * 256;
                int r = f >> 4, c4 = (f & 15) * 4;
                cp_async16(&Kw[r * AST + c4],
                           &kb[(size_t)(y0 + BKT + r) * DH + c4]);
                cp_async16(&Vw[r * AST + c4],
                           &vtb[(size_t)r * SEQ + y0 + BKT + c4]);
            }
            cp_commit();
            cp_wait<1>();      // tile i's group complete; i+1 in flight
        } else {
            cp_wait<0>();
        }
        __syncthreads();       // tile i data visible to all warps

        const float* Kb = &Ks[buf * KV_T];
        const float* Vb = &Vt[buf * KV_T];

        // ---- S = Q K^T (Q from registers) ----
        float s[8][4];
        #pragma unroll
        for (int nf = 0; nf < 8; nf++)
            #pragma unroll
            for (int e = 0; e < 4; e++) s[nf][e] = 0.f;

        #pragma unroll
        for (int kk = 0; kk < 8; kk++) {
            int kb8 = kk * 8 + 2 * lc;
            #pragma unroll
            for (int nf = 0; nf < 8; nf++) {
                float2 kk2 = *(const float2*)&Kb[(nf * 8 + lr) * AST + kb8];
                float b[2] = {kk2.x, kk2.y};
                mma_tf32(s[nf], qa[kk], b);
            }
        }

        // ---- causal mask (logical y cols; straddling tiles only) ----
        if (y0 + BKT - 1 > x0) {
            int r_lo = x0 + m_base + lr;
            #pragma unroll
            for (int nf = 0; nf < 8; nf++) {
                int c = y0 + nf * 8 + 2 * lc;
                if (c     > r_lo) s[nf][0] = -INFINITY;
                if (c + 1 > r_lo) s[nf][1] = -INFINITY;
                if (c     > r_lo + 8) s[nf][2] = -INFINITY;
                if (c + 1 > r_lo + 8) s[nf][3] = -INFINITY;
            }
        }

        // ---- online softmax (4-lane row groups) ----
        float mt_lo = -INFINITY, mt_hi = -INFINITY;
        #pragma unroll
        for (int nf = 0; nf < 8; nf++) {
            mt_lo = fmaxf(mt_lo, fmaxf(s[nf][0], s[nf][1]));
            mt_hi = fmaxf(mt_hi, fmaxf(s[nf][2], s[nf][3]));
        }
        #pragma unroll
        for (int off = 1; off <= 2; off <<= 1) {
            mt_lo = fmaxf(mt_lo, __shfl_xor_sync(0xffffffffu, mt_lo, off));
            mt_hi = fmaxf(mt_hi, __shfl_xor_sync(0xffffffffu, mt_hi, off));
        }
        float mn_lo = fmaxf(m_lo, mt_lo);
        float mn_hi = fmaxf(m_hi, mt_hi);
        float al_lo = __expf(m_lo - mn_lo);
        float al_hi = __expf(m_hi - mn_hi);
        m_lo = mn_lo; m_hi = mn_hi;

        float rs_lo = 0.f, rs_hi = 0.f;
        #pragma unroll
        for (int nf = 0; nf < 8; nf++) {
            s[nf][0] = __expf(s[nf][0] - mn_lo);
            s[nf][1] = __expf(s[nf][1] - mn_lo);
            s[nf][2] = __expf(s[nf][2] - mn_hi);
            s[nf][3] = __expf(s[nf][3] - mn_hi);
            rs_lo += s[nf][0] + s[nf][1];
            rs_hi += s[nf][2] + s[nf][3];
        }
        #pragma unroll
        for (int off = 1; off <= 2; off <<= 1) {
            rs_lo += __shfl_xor_sync(0xffffffffu, rs_lo, off);
            rs_hi += __shfl_xor_sync(0xffffffffu, rs_hi, off);
        }
        l_lo = l_lo * al_lo + rs_lo;
        l_hi = l_hi * al_hi + rs_hi;
        #pragma unroll
        for (int nf = 0; nf < 8; nf++) {
            o[nf][0] *= al_lo; o[nf][1] *= al_lo;
            o[nf][2] *= al_hi; o[nf][3] *= al_hi;
        }

        // ---- stage P (warp-private; y permuted per-8, tf32) ----
        #pragma unroll
        for (int nf = 0; nf < 8; nf++) {
            int q0 = nf * 8 + pp0;
            int q1 = nf * 8 + pp1;
            Pw[lr * AST + q0]       = f_tf32(s[nf][0]);
            Pw[lr * AST + q1]       = f_tf32(s[nf][1]);
            Pw[(lr + 8) * AST + q0] = f_tf32(s[nf][2]);
            Pw[(lr + 8) * AST + q1] = f_tf32(s[nf][3]);
        }
        __syncwarp();

        // ---- O += P V ----
        #pragma unroll
        for (int kk = 0; kk < 8; kk++) {
            int kb8 = kk * 8 + 2 * lc;
            float2 plo = *(const float2*)&Pw[lr * AST + kb8];
            float2 phi = *(const float2*)&Pw[(lr + 8) * AST + kb8];
            float a[4] = {plo.x, phi.x, plo.y, phi.y};
            #pragma unroll
            for (int nf = 0; nf < 8; nf++) {
                float2 vv = *(const float2*)&Vb[(nf * 8 + lr) * AST + kb8];
                float b[2] = {vv.x, vv.y};
                mma_tf32(o[nf], a, b);
            }
        }
        __syncwarp();
        __syncthreads();       // all warps done reading buf before it's refilled
        buf ^= 1;
    }

    // ---- normalize + store (permuted d cols, tf32: feeds o-proj) ----
    float inv_lo = 1.0f / l_lo;
    float inv_hi = 1.0f / l_hi;
    int r_lo = x0 + m_base + lr;
    #pragma unroll
    for (int nf = 0; nf < 8; nf++) {
        int dbase = h * HD + nf * 8;
        float* zlo = &z[((size_t)n * SEQ + r_lo) * DH + dbase];
        float* zhi = &z[((size_t)n * SEQ + r_lo + 8) * DH + dbase];
        zlo[pp0] = f_tf32(o[nf][0] * inv_lo);
        zlo[pp1] = f_tf32(o[nf][1] * inv_lo);
        zhi[pp0] = f_tf32(o[nf][2] * inv_hi);
        zhi[pp1] = f_tf32(o[nf][3] * inv_hi);
    }
}

// ------------------------------ launcher --------------------------------------
extern "C" void kernel_launch(void* const* d_in, const int* in_sizes, int n_in,
                              void* d_out, int out_size)
{
    const float* x     = (const float*)d_in[0];
    const float* Wq    = (const float*)d_in[1];
    const float* bq    = (const float*)d_in[2];
    const float* Wk    = (const float*)d_in[3];
    const float* bk    = (const float*)d_in[4];
    const float* Wv    = (const float*)d_in[5];
    const float* bv    = (const float*)d_in[6];
    const float* Wo    = (const float*)d_in[7];
    const float* bo    = (const float*)d_in[8];
    const float* gamma = (const float*)d_in[9];
    const float* beta  = (const float*)d_in[10];
    float* out = (float*)d_out;

    float *xn, *qp, *kp, *vp, *zp, *wt, *bqkv;
    cudaGetSymbolAddress((void**)&xn, g_xn);
    cudaGetSymbolAddress((void**)&qp, g_q);
    cudaGetSymbolAddress((void**)&kp, g_k);
    cudaGetSymbolAddress((void**)&vp, g_v);
    cudaGetSymbolAddress((void**)&zp, g_z);
    cudaGetSymbolAddress((void**)&wt, g_wt);
    cudaGetSymbolAddress((void**)&bqkv, g_bqkv);
    float* wqkv = wt;
    float* wo   = wt + 3 * DH * DH;

    cudaFuncSetAttribute(gemm_qkv_kernel,
                         cudaFuncAttributeMaxDynamicSharedMemorySize, GEMM_SMEM);
    cudaFuncSetAttribute(gemm_o_kernel,
                         cudaFuncAttributeMaxDynamicSharedMemorySize, GEMM_SMEM);
    cudaFuncSetAttribute(attn_kernel,
                         cudaFuncAttributeMaxDynamicSharedMemorySize, ATTN_SMEM);

    // 0. weights: tf32 + permute; biases: pack
    dim3 wgrid(DH * DH / 1024, 4);
    wcvt_kernel<<<wgrid, 256>>>(Wq, Wk, Wv, Wo, wt);
    bpack_kernel<<<DH / 256, 256>>>(bq, bk, bv, bqkv);

    // 1. LayerNorm (tf32 + permuted out)
    ln_kernel<<<MROWS / 8, 256>>>(x, gamma, beta, xn);

    // 2. fused QKV projection
    dim3 qkvgrid(3 * GN / 128, GM / 128);
    gemm_qkv_kernel<<<qkvgrid, 256, GEMM_SMEM>>>(xn, wqkv, bqkv, qp, kp, vp);

    // 3. causal multi-head attention
    dim3 agrid(SEQ / BQ, NH, NB);
    attn_kernel<<<agrid, 256, ATTN_SMEM>>>(qp, kp, vp, zp);

    // 4. output projection (standard-layout fp32 output)
    dim3 ogrid(GN / 128, GM / 128);
    gemm_o_kernel<<<ogrid, 256, GEMM_SMEM>>>(zp, wo, bo, out);
}

// round 13
// speedup vs baseline: 1.0738x; 1.0738x over previous
#include <cuda_runtime.h>
#include <cuda_bf16.h>
#include <math.h>
#include <stdint.h>

#define NB   4
#define SEQ  2048
#define DH   1024
#define NH   16
#define HD   64
#define MROWS (NB*SEQ)
#define GM MROWS
#define GN DH
#define GK DH

__device__ float g_xn[MROWS * DH];      // A-fragment order
__device__ float g_q [MROWS * DH];      // permuted cols (pi8)
__device__ float g_k [MROWS * DH];      // permuted cols
__device__ float g_v [MROWS * DH];      // transposed [NB][NH][HD][SEQ], y permuted
__device__ float g_z [MROWS * DH];      // A-fragment order
__device__ float g_wt[4][DH * DH];      // tf32, B-fragment order
__device__ float g_bqkv[3 * DH];

__device__ __forceinline__ int pi8(int j) { return ((j & 3) << 1) | (j >> 2); }

__device__ __forceinline__ float f_tf32(float x) {
    uint32_t r;
    asm("cvt.rna.tf32.f32 %0, %1;" : "=r"(r) : "f"(x));
    return __uint_as_float(r);
}

__device__ __forceinline__ void mma_tf32(float* c, const float* a, const float* b) {
    asm volatile(
        "mma.sync.aligned.m16n8k8.row.col.f32.tf32.tf32.f32 "
        "{%0,%1,%2,%3}, {%4,%5,%6,%7}, {%8,%9}, {%0,%1,%2,%3};\n"
        : "+f"(c[0]), "+f"(c[1]), "+f"(c[2]), "+f"(c[3])
        : "r"(__float_as_uint(a[0])), "r"(__float_as_uint(a[1])),
          "r"(__float_as_uint(a[2])), "r"(__float_as_uint(a[3])),
          "r"(__float_as_uint(b[0])), "r"(__float_as_uint(b[1])));
}

__device__ __forceinline__ void cp_async16(void* smem, const void* gmem) {
    uint32_t s = (uint32_t)__cvta_generic_to_shared(smem);
    asm volatile("cp.async.cg.shared.global [%0], [%1], 16;" :: "r"(s), "l"(gmem));
}
__device__ __forceinline__ void cp_commit() { asm volatile("cp.async.commit_group;"); }
template<int N>
__device__ __forceinline__ void cp_wait() {
    asm volatile("cp.async.wait_group %0;" :: "n"(N));
}

// A-fragment index: row r (global), logical k. Unit = {A[r][klo],A[r+8][klo],A[r][khi],A[r+8][khi]}
__device__ __forceinline__ size_t afrag_idx(int r, int k) {
    int m128 = r >> 7, rl = r & 127;
    int wm = rl >> 6, mf = (rl >> 4) & 3, er = (rl >> 3) & 1, lr = rl & 7;
    int kt = k >> 5, kk = (k >> 3) & 3, ek = (k >> 2) & 1, lc = k & 3;
    return (size_t)m128 * 131072 + kt * 4096
         + (((((kk * 2 + wm) * 4 + mf) * 8 + lr) * 4 + lc) << 2) + er + 2 * ek;
}

// ---- weight cvt: tf32 + B-fragment order ----
__global__ __launch_bounds__(256) void wcvt_kernel(
    const float* __restrict__ w0, const float* __restrict__ w1,
    const float* __restrict__ w2, const float* __restrict__ w3,
    float* __restrict__ dst)
{
    const float* srcs[4] = {w0, w1, w2, w3};
    const float* src = srcs[blockIdx.y];
    float* d = dst + (size_t)blockIdx.y * DH * DH;
    int i = (blockIdx.x * 256 + threadIdx.x) * 4;
    int ncol = i >> 10, k = i & 1023;          // 4 consecutive k, lc=0..3
    float4 v = *(const float4*)&src[i];

    int n128 = ncol >> 7, nloc = ncol & 127;
    int wn = nloc >> 5, nf = (nloc >> 3) & 3, lr = nloc & 7;
    int kt = k >> 5, kk = (k >> 3) & 3, ek = (k >> 2) & 1;
    size_t base = (size_t)n128 * 131072 + kt * 4096 + (nf >> 1) * 2048
                + (nf & 1) * 2 + ek;
    int U0 = ((kk * 4 + wn) * 8 + lr) * 4;     // + lc, each unit 4 floats
    d[base + (size_t)(U0 + 0) * 4] = f_tf32(v.x);
    d[base + (size_t)(U0 + 1) * 4] = f_tf32(v.y);
    d[base + (size_t)(U0 + 2) * 4] = f_tf32(v.z);
    d[base + (size_t)(U0 + 3) * 4] = f_tf32(v.w);
}

__global__ __launch_bounds__(256) void bpack_kernel(
    const float* __restrict__ b0, const float* __restrict__ b1,
    const float* __restrict__ b2, float* __restrict__ dst)
{
    int i = blockIdx.x * 256 + threadIdx.x;
    dst[i] = b0[i]; dst[i + DH] = b1[i]; dst[i + 2 * DH] = b2[i];
}

// ---- LayerNorm: warp/row, tf32, A-fragment out ----
__global__ __launch_bounds__(256) void ln_kernel(
    const float* __restrict__ x, const float* __restrict__ gamma,
    const float* __restrict__ beta, float* __restrict__ xn)
{
    int warp = threadIdx.x >> 5, lane = threadIdx.x & 31;
    int row = blockIdx.x * 8 + warp;
    const float* xr = x + (size_t)row * DH;

    float4 v[8];
    float s = 0.f, sq = 0.f;
    #pragma unroll
    for (int j = 0; j < 8; j++) {
        v[j] = *(const float4*)&xr[(j * 32 + lane) * 4];
        s  += v[j].x + v[j].y + v[j].z + v[j].w;
        sq += v[j].x * v[j].x + v[j].y * v[j].y
            + v[j].z * v[j].z + v[j].w * v[j].w;
    }
    #pragma unroll
    for (int off = 16; off > 0; off >>= 1) {
        s  += __shfl_xor_sync(0xffffffffu, s,  off);
        sq += __shfl_xor_sync(0xffffffffu, sq, off);
    }
    float mu  = s * (1.0f / DH);
    float var = sq * (1.0f / DH) - mu * mu;
    float inv = rsqrtf(var + 1e-5f);

    #pragma unroll
    for (int j = 0; j < 8; j++) {
        int c = (j * 32 + lane) * 4;
        float4 g = *(const float4*)&gamma[c];
        float4 b = *(const float4*)&beta[c];
        size_t i0 = afrag_idx(row, c);          // c%4==0: lc=0..3 stride 4
        xn[i0]      = f_tf32((v[j].x - mu) * inv * g.x + b.x);
        xn[i0 + 4]  = f_tf32((v[j].y - mu) * inv * g.y + b.y);
        xn[i0 + 8]  = f_tf32((v[j].z - mu) * inv * g.z + b.z);
        xn[i0 + 12] = f_tf32((v[j].w - mu) * inv * g.w + b.w);
    }
}

// ---- GEMM core: fragment-order operands, flat cp.async, LDS.128 ----
#define GTILE 4096
#define GEMM_SMEM (4 * GTILE * (int)sizeof(float))

struct GemmCore {
    float acc[4][4][4];
    int t, lr, lc, wm, wn, m_base, n_base;

    __device__ __forceinline__ void init(int tid) {
        t = tid;
        int lane = t & 31, wid = t >> 5;
        lr = lane >> 2; lc = lane & 3;
        wm = wid & 1; wn = wid >> 1;
        m_base = wm * 64; n_base = wn * 32;
        #pragma unroll
        for (int i = 0; i < 4; i++)
            #pragma unroll
            for (int j = 0; j < 4; j++)
                #pragma unroll
                for (int e = 0; e < 4; e++) acc[i][j][e] = 0.f;
    }

    __device__ __forceinline__ void run(
        float* As, float* Bs,
        const float* __restrict__ At, const float* __restrict__ Bt)
    {
        #pragma unroll
        for (int i = 0; i < 4; i++) {
            int f4 = (t + i * 256) * 4;
            cp_async16(&As[f4], &At[f4]);
            cp_async16(&Bs[f4], &Bt[f4]);
        }
        cp_commit();

        int buf = 0;
        for (int kt = 0; kt < 32; kt++) {
            bool more = (kt + 1 < 32);
            cp_wait<0>();
            __syncthreads();

            if (more) {
                float* Aw = &As[(buf ^ 1) * GTILE];
                float* Bw = &Bs[(buf ^ 1) * GTILE];
                const float* Ag = At + (size_t)(kt + 1) * GTILE;
                const float* Bg = Bt + (size_t)(kt + 1) * GTILE;
                #pragma unroll
                for (int i = 0; i < 4; i++) {
                    int f4 = (t + i * 256) * 4;
                    cp_async16(&Aw[f4], &Ag[f4]);
                    cp_async16(&Bw[f4], &Bg[f4]);
                }
                cp_commit();
            }

            const float* Ab = &As[buf * GTILE];
            const float* Bb = &Bs[buf * GTILE];
            #pragma unroll
            for (int kk = 0; kk < 4; kk++) {
                float a[4][4], b[4][2];
                #pragma unroll
                for (int mf = 0; mf < 4; mf++) {
                    float4 av = *(const float4*)
                        &Ab[(((((kk * 2 + wm) * 4 + mf) * 8 + lr) * 4 + lc) << 2)];
                    a[mf][0] = av.x; a[mf][1] = av.y;
                    a[mf][2] = av.z; a[mf][3] = av.w;
                }
                int U = (((kk * 4 + wn) * 8 + lr) * 4 + lc) << 2;
                float4 b01 = *(const float4*)&Bb[U];
                float4 b23 = *(const float4*)&Bb[2048 + U];
                b[0][0] = b01.x; b[0][1] = b01.y;
                b[1][0] = b01.z; b[1][1] = b01.w;
                b[2][0] = b23.x; b[2][1] = b23.y;
                b[3][0] = b23.z; b[3][1] = b23.w;
                #pragma unroll
                for (int mf = 0; mf < 4; mf++)
                    #pragma unroll
                    for (int nf = 0; nf < 4; nf++)
                        mma_tf32(acc[mf][nf], a[mf], b[nf]);
            }
            buf ^= 1;
        }
    }
};

// Fused QKV. A: afrag. Wp: bfrag packed [q|k|v]. Outputs unchanged layouts.
__global__ __launch_bounds__(256, 2) void gemm_qkv_kernel(
    const float* __restrict__ A, const float* __restrict__ Wp,
    const float* __restrict__ bp,
    float* __restrict__ q, float* __restrict__ k, float* __restrict__ v)
{
    extern __shared__ float gsm[];
    GemmCore core;
    core.init(threadIdx.x);

    int npack0 = blockIdx.x * 128;
    int m0 = blockIdx.y * 128;
    int mat = npack0 >> 10;
    int ncol0 = npack0 & 1023;

    core.run(gsm, gsm + 2 * GTILE,
             A  + (size_t)blockIdx.y * 131072,
             Wp + (size_t)blockIdx.x * 131072);

    const float* bias = bp + npack0;
    int lr = core.lr, lc = core.lc;
    int p0 = pi8(2 * lc), p1 = pi8(2 * lc + 1);

    #pragma unroll
    for (int nf = 0; nf < 4; nf++) {
        int cb = core.n_base + nf * 8;
        float b0 = bias[cb + 2 * lc];
        float b1 = bias[cb + 2 * lc + 1];
        #pragma unroll
        for (int mf = 0; mf < 4; mf++) {
            int row = m0 + core.m_base + mf * 16 + lr;
            float v0 = f_tf32(core.acc[mf][nf][0] + b0);
            float v1 = f_tf32(core.acc[mf][nf][1] + b1);
            float v2 = f_tf32(core.acc[mf][nf][2] + b0);
            float v3 = f_tf32(core.acc[mf][nf][3] + b1);
            if (mat == 2) {
                int c0 = ncol0 + cb + 2 * lc;
                int yl = row & (SEQ - 1);
                int py = (yl & ~7) | pi8(yl & 7);
                size_t b_ = (size_t)(row >> 11) * DH;
                v[(b_ + c0)     * SEQ + py]     = v0;
                v[(b_ + c0 + 1) * SEQ + py]     = v1;
                v[(b_ + c0)     * SEQ + py + 8] = v2;
                v[(b_ + c0 + 1) * SEQ + py + 8] = v3;
            } else {
                float* C = (mat == 0) ? q : k;
                int colb = ncol0 + cb;
                C[(size_t)row * GN + colb + p0]       = v0;
                C[(size_t)row * GN + colb + p1]       = v1;
                C[(size_t)(row + 8) * GN + colb + p0] = v2;
                C[(size_t)(row + 8) * GN + colb + p1] = v3;
            }
        }
    }
}

// Output projection: A (z, afrag), W (bfrag). Standard-layout fp32 output.
__global__ __launch_bounds__(256, 2) void gemm_o_kernel(
    const float* __restrict__ A, const float* __restrict__ W,
    const float* __restrict__ bias, float* __restrict__ C)
{
    extern __shared__ float gsm[];
    GemmCore core;
    core.init(threadIdx.x);
    int n0 = blockIdx.x * 128;
    int m0 = blockIdx.y * 128;
    core.run(gsm, gsm + 2 * GTILE,
             A + (size_t)blockIdx.y * 131072,
             W + (size_t)blockIdx.x * 131072);

    int lr = core.lr, lc = core.lc;
    #pragma unroll
    for (int nf = 0; nf < 4; nf++) {
        int col = n0 + core.n_base + nf * 8 + 2 * lc;
        float b0 = bias[col], b1 = bias[col + 1];
        #pragma unroll
        for (int mf = 0; mf < 4; mf++) {
            int row = m0 + core.m_base + mf * 16 + lr;
            *(float2*)&C[(size_t)row * GN + col] =
                make_float2(core.acc[mf][nf][0] + b0, core.acc[mf][nf][1] + b1);
            *(float2*)&C[(size_t)(row + 8) * GN + col] =
                make_float2(core.acc[mf][nf][2] + b0, core.acc[mf][nf][3] + b1);
        }
    }
}

// ---- Flash Attention: round-10 code; z epilogue writes afrag order ----
#define BQ  128
#define BKT 64
#define AST 72
#define KV_T (BKT * AST)
#define ATTN_SMEM ((4*KV_T + BQ*AST) * (int)sizeof(float))

__global__ __launch_bounds__(256, 2) void attn_kernel(
    const float* __restrict__ q, const float* __restrict__ k,
    const float* __restrict__ v, float* __restrict__ z)
{
    extern __shared__ float sm[];
    float* Ks = sm;
    float* Vt = sm + 2 * KV_T;
    float* Ps = sm + 4 * KV_T;

    int xc = (gridDim.x - 1) - blockIdx.x;
    int h  = blockIdx.y;
    int n  = blockIdx.z;
    int x0 = xc * BQ;
    int t    = threadIdx.x;
    int lane = t & 31;
    int wid  = t >> 5;
    int lr = lane >> 2;
    int lc = lane & 3;
    int m_base = wid * 16;
    float* Pw = Ps + m_base * AST;
    int pp0 = pi8(2 * lc), pp1 = pi8(2 * lc + 1);

    const float* qb = q + ((size_t)n * SEQ) * DH + h * HD;
    const float* kb = k + ((size_t)n * SEQ) * DH + h * HD;
    const float* vtb = v + ((size_t)(n * NH + h) * HD) * SEQ;

    #pragma unroll
    for (int i = 0; i < 4; i++) {
        int f = t + i * 256;
        int r = f >> 4, c4 = (f & 15) * 4;
        cp_async16(&Ks[r * AST + c4], &kb[(size_t)r * DH + c4]);
        cp_async16(&Vt[r * AST + c4], &vtb[(size_t)r * SEQ + c4]);
    }
    cp_commit();

    float qa[8][4];
    #pragma unroll
    for (int kk = 0; kk < 8; kk++) {
        float2 lo = *(const float2*)&qb[(size_t)(x0 + m_base + lr) * DH + kk * 8 + 2 * lc];
        float2 hi = *(const float2*)&qb[(size_t)(x0 + m_base + lr + 8) * DH + kk * 8 + 2 * lc];
        qa[kk][0] = lo.x * 0.125f; qa[kk][1] = hi.x * 0.125f;
        qa[kk][2] = lo.y * 0.125f; qa[kk][3] = hi.y * 0.125f;
    }

    float m_lo = -INFINITY, m_hi = -INFINITY, l_lo = 0.f, l_hi = 0.f;
    float o[8][4];
    #pragma unroll
    for (int nf = 0; nf < 8; nf++)
        #pragma unroll
        for (int e = 0; e < 4; e++) o[nf][e] = 0.f;

    int yend = x0 + BQ;
    int buf = 0;
    for (int y0 = 0; y0 < yend; y0 += BKT) {
        bool more = (y0 + BKT < yend);
        if (more) {
            float* Kw = &Ks[(buf ^ 1) * KV_T];
            float* Vw = &Vt[(buf ^ 1) * KV_T];
            #pragma unroll
            for (int i = 0; i < 4; i++) {
                int f = t + i * 256;
                int r = f >> 4, c4 = (f & 15) * 4;
                cp_async16(&Kw[r * AST + c4], &kb[(size_t)(y0 + BKT + r) * DH + c4]);
                cp_async16(&Vw[r * AST + c4], &vtb[(size_t)r * SEQ + y0 + BKT + c4]);
            }
            cp_commit();
            cp_wait<1>();
        } else {
            cp_wait<0>();
        }
        __syncthreads();

        const float* Kb = &Ks[buf * KV_T];
        const float* Vb = &Vt[buf * KV_T];

        float s[8][4];
        #pragma unroll
        for (int nf = 0; nf < 8; nf++)
            #pragma unroll
            for (int e = 0; e < 4; e++) s[nf][e] = 0.f;

        #pragma unroll
        for (int kk = 0; kk < 8; kk++) {
            int kb8 = kk * 8 + 2 * lc;
            #pragma unroll
            for (int nf = 0; nf < 8; nf++) {
                float2 kk2 = *(const float2*)&Kb[(nf * 8 + lr) * AST + kb8];
                float b[2] = {kk2.x, kk2.y};
                mma_tf32(s[nf], qa[kk], b);
            }
        }

        if (y0 + BKT - 1 > x0) {
            int r_lo = x0 + m_base + lr;
            #pragma unroll
            for (int nf = 0; nf < 8; nf++) {
                int c = y0 + nf * 8 + 2 * lc;
                if (c     > r_lo) s[nf][0] = -INFINITY;
                if (c + 1 > r_lo) s[nf][1] = -INFINITY;
                if (c     > r_lo + 8) s[nf][2] = -INFINITY;
                if (c + 1 > r_lo + 8) s[nf][3] = -INFINITY;
            }
        }

        float mt_lo = -INFINITY, mt_hi = -INFINITY;
        #pragma unroll
        for (int nf = 0; nf < 8; nf++) {
            mt_lo = fmaxf(mt_lo, fmaxf(s[nf][0], s[nf][1]));
            mt_hi = fmaxf(mt_hi, fmaxf(s[nf][2], s[nf][3]));
        }
        #pragma unroll
        for (int off = 1; off <= 2; off <<= 1) {
            mt_lo = fmaxf(mt_lo, __shfl_xor_sync(0xffffffffu, mt_lo, off));
            mt_hi = fmaxf(mt_hi, __shfl_xor_sync(0xffffffffu, mt_hi, off));
        }
        float mn_lo = fmaxf(m_lo, mt_lo);
        float mn_hi = fmaxf(m_hi, mt_hi);
        float al_lo = __expf(m_lo - mn_lo);
        float al_hi = __expf(m_hi - mn_hi);
        m_lo = mn_lo; m_hi = mn_hi;

        float rs_lo = 0.f, rs_hi = 0.f;
        #pragma unroll
        for (int nf = 0; nf < 8; nf++) {
            s[nf][0] = __expf(s[nf][0] - mn_lo);
            s[nf][1] = __expf(s[nf][1] - mn_lo);
            s[nf][2] = __expf(s[nf][2] - mn_hi);
            s[nf][3] = __expf(s[nf][3] - mn_hi);
            rs_lo += s[nf][0] + s[nf][1];
            rs_hi += s[nf][2] + s[nf][3];
        }
        #pragma unroll
        for (int off = 1; off <= 2; off <<= 1) {
            rs_lo += __shfl_xor_sync(0xffffffffu, rs_lo, off);
            rs_hi += __shfl_xor_sync(0xffffffffu, rs_hi, off);
        }
        l_lo = l_lo * al_lo + rs_lo;
        l_hi = l_hi * al_hi + rs_hi;
        #pragma unroll
        for (int nf = 0; nf < 8; nf++) {
            o[nf][0] *= al_lo; o[nf][1] *= al_lo;
            o[nf][2] *= al_hi; o[nf][3] *= al_hi;
        }

        #pragma unroll
        for (int nf = 0; nf < 8; nf++) {
            int q0 = nf * 8 + pp0;
            int q1 = nf * 8 + pp1;
            Pw[lr * AST + q0]       = f_tf32(s[nf][0]);
            Pw[lr * AST + q1]       = f_tf32(s[nf][1]);
            Pw[(lr + 8) * AST + q0] = f_tf32(s[nf][2]);
            Pw[(lr + 8) * AST + q1] = f_tf32(s[nf][3]);
        }
        __syncwarp();

        #pragma unroll
        for (int kk = 0; kk < 8; kk++) {
            int kb8 = kk * 8 + 2 * lc;
            float2 plo = *(const float2*)&Pw[lr * AST + kb8];
            float2 phi = *(const float2*)&Pw[(lr + 8) * AST + kb8];
            float a[4] = {plo.x, phi.x, plo.y, phi.y};
            #pragma unroll
            for (int nf = 0; nf < 8; nf++) {
                float2 vv = *(const float2*)&Vb[(nf * 8 + lr) * AST + kb8];
                float b[2] = {vv.x, vv.y};
                mma_tf32(o[nf], a, b);
            }
        }
        __syncwarp();
        __syncthreads();
        buf ^= 1;
    }

    // normalize + store z in A-FRAGMENT order (true d cols) for o-proj
    float inv_lo = 1.0f / l_lo;
    float inv_hi = 1.0f / l_hi;
    int grow = (int)((size_t)n * SEQ) + x0 + m_base + lr;
    #pragma unroll
    for (int nf = 0; nf < 8; nf++) {
        int d0 = h * HD + nf * 8 + 2 * lc;
        z[afrag_idx(grow, d0)]         = f_tf32(o[nf][0] * inv_lo);
        z[afrag_idx(grow, d0 + 1)]     = f_tf32(o[nf][1] * inv_lo);
        z[afrag_idx(grow + 8, d0)]     = f_tf32(o[nf][2] * inv_hi);
        z[afrag_idx(grow + 8, d0 + 1)] = f_tf32(o[nf][3] * inv_hi);
    }
}

// ------------------------------ launcher --------------------------------------
extern "C" void kernel_launch(void* const* d_in, const int* in_sizes, int n_in,
                              void* d_out, int out_size)
{
    const float* x     = (const float*)d_in[0];
    const float* Wq    = (const float*)d_in[1];
    const float* bq    = (const float*)d_in[2];
    const float* Wk    = (const float*)d_in[3];
    const float* bk    = (const float*)d_in[4];
    const float* Wv    = (const float*)d_in[5];
    const float* bv    = (const float*)d_in[6];
    const float* Wo    = (const float*)d_in[7];
    const float* bo    = (const float*)d_in[8];
    const float* gamma = (const float*)d_in[9];
    const float* beta  = (const float*)d_in[10];
    float* out = (float*)d_out;

    float *xn, *qp, *kp, *vp, *zp, *wt, *bqkv;
    cudaGetSymbolAddress((void**)&xn, g_xn);
    cudaGetSymbolAddress((void**)&qp, g_q);
    cudaGetSymbolAddress((void**)&kp, g_k);
    cudaGetSymbolAddress((void**)&vp, g_v);
    cudaGetSymbolAddress((void**)&zp, g_z);
    cudaGetSymbolAddress((void**)&wt, g_wt);
    cudaGetSymbolAddress((void**)&bqkv, g_bqkv);
    float* wqkv = wt;
    float* wo   = wt + 3 * DH * DH;

    cudaFuncSetAttribute(gemm_qkv_kernel,
                         cudaFuncAttributeMaxDynamicSharedMemorySize, GEMM_SMEM);
    cudaFuncSetAttribute(gemm_o_kernel,
                         cudaFuncAttributeMaxDynamicSharedMemorySize, GEMM_SMEM);
    cudaFuncSetAttribute(attn_kernel,
                         cudaFuncAttributeMaxDynamicSharedMemorySize, ATTN_SMEM);

    dim3 wgrid(DH * DH / 1024, 4);
    wcvt_kernel<<<wgrid, 256>>>(Wq, Wk, Wv, Wo, wt);
    bpack_kernel<<<DH / 256, 256>>>(bq, bk, bv, bqkv);

    ln_kernel<<<MROWS / 8, 256>>>(x, gamma, beta, xn);

    dim3 qkvgrid(3 * GN / 128, GM / 128);
    gemm_qkv_kernel<<<qkvgrid, 256, GEMM_SMEM>>>(xn, wqkv, bqkv, qp, kp, vp);

    dim3 agrid(SEQ / BQ, NH, NB);
    attn_kernel<<<agrid, 256, ATTN_SMEM>>>(qp, kp, vp, zp);

    dim3 ogrid(GN / 128, GM / 128);
    gemm_o_kernel<<<ogrid, 256, GEMM_SMEM>>>(zp, wo, bo, out);
}

// round 14
// speedup vs baseline: 1.0835x; 1.0090x over previous
#include <cuda_runtime.h>
#include <cuda_bf16.h>
#include <math.h>
#include <stdint.h>

#define NB   4
#define SEQ  2048
#define DH   1024
#define NH   16
#define HD   64
#define MROWS (NB*SEQ)
#define GM MROWS
#define GN DH
#define GK DH

__device__ float g_xn[MROWS * DH];      // A-fragment order
__device__ float g_q [MROWS * DH];      // permuted cols (pi8)
__device__ float g_k [MROWS * DH];      // K-fragment tiles [NB][NH][SEQ/64][4096]
__device__ float g_v [MROWS * DH];      // V-fragment tiles [NB][NH][SEQ/64][4096]
__device__ float g_z [MROWS * DH];      // A-fragment order
__device__ float g_wt[4][DH * DH];      // tf32, B-fragment order
__device__ float g_bqkv[3 * DH];

__device__ __forceinline__ int pi8(int j) { return ((j & 3) << 1) | (j >> 2); }

__device__ __forceinline__ float f_tf32(float x) {
    uint32_t r;
    asm("cvt.rna.tf32.f32 %0, %1;" : "=r"(r) : "f"(x));
    return __uint_as_float(r);
}

__device__ __forceinline__ void mma_tf32(float* c, const float* a, const float* b) {
    asm volatile(
        "mma.sync.aligned.m16n8k8.row.col.f32.tf32.tf32.f32 "
        "{%0,%1,%2,%3}, {%4,%5,%6,%7}, {%8,%9}, {%0,%1,%2,%3};\n"
        : "+f"(c[0]), "+f"(c[1]), "+f"(c[2]), "+f"(c[3])
        : "r"(__float_as_uint(a[0])), "r"(__float_as_uint(a[1])),
          "r"(__float_as_uint(a[2])), "r"(__float_as_uint(a[3])),
          "r"(__float_as_uint(b[0])), "r"(__float_as_uint(b[1])));
}

__device__ __forceinline__ void cp_async16(void* smem, const void* gmem) {
    uint32_t s = (uint32_t)__cvta_generic_to_shared(smem);
    asm volatile("cp.async.cg.shared.global [%0], [%1], 16;" :: "r"(s), "l"(gmem));
}
__device__ __forceinline__ void cp_commit() { asm volatile("cp.async.commit_group;"); }
template<int N>
__device__ __forceinline__ void cp_wait() {
    asm volatile("cp.async.wait_group %0;" :: "n"(N));
}

// A-fragment index (GEMM A / z): unit {A[r][klo],A[r+8][klo],A[r][khi],A[r+8][khi]}
__device__ __forceinline__ size_t afrag_idx(int r, int k) {
    int m128 = r >> 7, rl = r & 127;
    int wm = rl >> 6, mf = (rl >> 4) & 3, er = (rl >> 3) & 1, lr = rl & 7;
    int kt = k >> 5, kk = (k >> 3) & 3, ek = (k >> 2) & 1, lc = k & 3;
    return (size_t)m128 * 131072 + kt * 4096
         + (((((kk * 2 + wm) * 4 + mf) * 8 + lr) * 4 + lc) << 2) + er + 2 * ek;
}

// attention K tile (64y x 64d -> 4096 floats): B-fragment units, nf-paired regions
__device__ __forceinline__ int kfrag_idx(int yl, int dh) {
    int kk = dh >> 3, lcA = dh & 3, eA = (dh >> 2) & 1;
    int lrA = yl & 7, nfA = yl >> 3;
    return (nfA >> 1) * 1024 + (kk * 32 + lrA * 4 + lcA) * 4 + (nfA & 1) * 2 + eA;
}
// attention V tile: k-dim = y, n-dim = d
__device__ __forceinline__ int vfrag_idx(int yl, int dh) {
    int kk = yl >> 3, lcA = yl & 3, eA = (yl >> 2) & 1;
    int lrA = dh & 7, nfA = dh >> 3;
    return (nfA >> 1) * 1024 + (kk * 32 + lrA * 4 + lcA) * 4 + (nfA & 1) * 2 + eA;
}

// ---- weight cvt: tf32 + B-fragment order ----
__global__ __launch_bounds__(256) void wcvt_kernel(
    const float* __restrict__ w0, const float* __restrict__ w1,
    const float* __restrict__ w2, const float* __restrict__ w3,
    float* __restrict__ dst)
{
    const float* srcs[4] = {w0, w1, w2, w3};
    const float* src = srcs[blockIdx.y];
    float* d = dst + (size_t)blockIdx.y * DH * DH;
    int i = (blockIdx.x * 256 + threadIdx.x) * 4;
    int ncol = i >> 10, k = i & 1023;
    float4 v = *(const float4*)&src[i];

    int n128 = ncol >> 7, nloc = ncol & 127;
    int wn = nloc >> 5, nf = (nloc >> 3) & 3, lr = nloc & 7;
    int kt = k >> 5, kk = (k >> 3) & 3, ek = (k >> 2) & 1;
    size_t base = (size_t)n128 * 131072 + kt * 4096 + (nf >> 1) * 2048
                + (nf & 1) * 2 + ek;
    int U0 = ((kk * 4 + wn) * 8 + lr) * 4;
    d[base + (size_t)(U0 + 0) * 4] = f_tf32(v.x);
    d[base + (size_t)(U0 + 1) * 4] = f_tf32(v.y);
    d[base + (size_t)(U0 + 2) * 4] = f_tf32(v.z);
    d[base + (size_t)(U0 + 3) * 4] = f_tf32(v.w);
}

__global__ __launch_bounds__(256) void bpack_kernel(
    const float* __restrict__ b0, const float* __restrict__ b1,
    const float* __restrict__ b2, float* __restrict__ dst)
{
    int i = blockIdx.x * 256 + threadIdx.x;
    dst[i] = b0[i]; dst[i + DH] = b1[i]; dst[i + 2 * DH] = b2[i];
}

// ---- LayerNorm: warp/row, tf32, A-fragment out ----
__global__ __launch_bounds__(256) void ln_kernel(
    const float* __restrict__ x, const float* __restrict__ gamma,
    const float* __restrict__ beta, float* __restrict__ xn)
{
    int warp = threadIdx.x >> 5, lane = threadIdx.x & 31;
    int row = blockIdx.x * 8 + warp;
    const float* xr = x + (size_t)row * DH;

    float4 v[8];
    float s = 0.f, sq = 0.f;
    #pragma unroll
    for (int j = 0; j < 8; j++) {
        v[j] = *(const float4*)&xr[(j * 32 + lane) * 4];
        s  += v[j].x + v[j].y + v[j].z + v[j].w;
        sq += v[j].x * v[j].x + v[j].y * v[j].y
            + v[j].z * v[j].z + v[j].w * v[j].w;
    }
    #pragma unroll
    for (int off = 16; off > 0; off >>= 1) {
        s  += __shfl_xor_sync(0xffffffffu, s,  off);
        sq += __shfl_xor_sync(0xffffffffu, sq, off);
    }
    float mu  = s * (1.0f / DH);
    float var = sq * (1.0f / DH) - mu * mu;
    float inv = rsqrtf(var + 1e-5f);

    #pragma unroll
    for (int j = 0; j < 8; j++) {
        int c = (j * 32 + lane) * 4;
        float4 g = *(const float4*)&gamma[c];
        float4 b = *(const float4*)&beta[c];
        size_t i0 = afrag_idx(row, c);
        xn[i0]      = f_tf32((v[j].x - mu) * inv * g.x + b.x);
        xn[i0 + 4]  = f_tf32((v[j].y - mu) * inv * g.y + b.y);
        xn[i0 + 8]  = f_tf32((v[j].z - mu) * inv * g.z + b.z);
        xn[i0 + 12] = f_tf32((v[j].w - mu) * inv * g.w + b.w);
    }
}

// ---- GEMM core: fragment-order operands, flat cp.async, LDS.128 ----
#define GTILE 4096
#define GEMM_SMEM (4 * GTILE * (int)sizeof(float))

struct GemmCore {
    float acc[4][4][4];
    int t, lr, lc, wm, wn, m_base, n_base;

    __device__ __forceinline__ void init(int tid) {
        t = tid;
        int lane = t & 31, wid = t >> 5;
        lr = lane >> 2; lc = lane & 3;
        wm = wid & 1; wn = wid >> 1;
        m_base = wm * 64; n_base = wn * 32;
        #pragma unroll
        for (int i = 0; i < 4; i++)
            #pragma unroll
            for (int j = 0; j < 4; j++)
                #pragma unroll
                for (int e = 0; e < 4; e++) acc[i][j][e] = 0.f;
    }

    __device__ __forceinline__ void run(
        float* As, float* Bs,
        const float* __restrict__ At, const float* __restrict__ Bt)
    {
        #pragma unroll
        for (int i = 0; i < 4; i++) {
            int f4 = (t + i * 256) * 4;
            cp_async16(&As[f4], &At[f4]);
            cp_async16(&Bs[f4], &Bt[f4]);
        }
        cp_commit();

        int buf = 0;
        for (int kt = 0; kt < 32; kt++) {
            bool more = (kt + 1 < 32);
            cp_wait<0>();
            __syncthreads();

            if (more) {
                float* Aw = &As[(buf ^ 1) * GTILE];
                float* Bw = &Bs[(buf ^ 1) * GTILE];
                const float* Ag = At + (size_t)(kt + 1) * GTILE;
                const float* Bg = Bt + (size_t)(kt + 1) * GTILE;
                #pragma unroll
                for (int i = 0; i < 4; i++) {
                    int f4 = (t + i * 256) * 4;
                    cp_async16(&Aw[f4], &Ag[f4]);
                    cp_async16(&Bw[f4], &Bg[f4]);
                }
                cp_commit();
            }

            const float* Ab = &As[buf * GTILE];
            const float* Bb = &Bs[buf * GTILE];
            #pragma unroll
            for (int kk = 0; kk < 4; kk++) {
                float a[4][4], b[4][2];
                #pragma unroll
                for (int mf = 0; mf < 4; mf++) {
                    float4 av = *(const float4*)
                        &Ab[(((((kk * 2 + wm) * 4 + mf) * 8 + lr) * 4 + lc) << 2)];
                    a[mf][0] = av.x; a[mf][1] = av.y;
                    a[mf][2] = av.z; a[mf][3] = av.w;
                }
                int U = (((kk * 4 + wn) * 8 + lr) * 4 + lc) << 2;
                float4 b01 = *(const float4*)&Bb[U];
                float4 b23 = *(const float4*)&Bb[2048 + U];
                b[0][0] = b01.x; b[0][1] = b01.y;
                b[1][0] = b01.z; b[1][1] = b01.w;
                b[2][0] = b23.x; b[2][1] = b23.y;
                b[3][0] = b23.z; b[3][1] = b23.w;
                #pragma unroll
                for (int mf = 0; mf < 4; mf++)
                    #pragma unroll
                    for (int nf = 0; nf < 4; nf++)
                        mma_tf32(acc[mf][nf], a[mf], b[nf]);
            }
            buf ^= 1;
        }
    }
};

// Fused QKV. Writes q permuted-row-major; k,v fragment-ordered head tiles.
__global__ __launch_bounds__(256, 2) void gemm_qkv_kernel(
    const float* __restrict__ A, const float* __restrict__ Wp,
    const float* __restrict__ bp,
    float* __restrict__ q, float* __restrict__ k, float* __restrict__ v)
{
    extern __shared__ float gsm[];
    GemmCore core;
    core.init(threadIdx.x);

    int npack0 = blockIdx.x * 128;
    int m0 = blockIdx.y * 128;
    int mat = npack0 >> 10;
    int ncol0 = npack0 & 1023;

    core.run(gsm, gsm + 2 * GTILE,
             A  + (size_t)blockIdx.y * 131072,
             Wp + (size_t)blockIdx.x * 131072);

    const float* bias = bp + npack0;
    int lr = core.lr, lc = core.lc;
    int p0 = pi8(2 * lc), p1 = pi8(2 * lc + 1);

    #pragma unroll
    for (int nf = 0; nf < 4; nf++) {
        int cb = core.n_base + nf * 8;
        float b0 = bias[cb + 2 * lc];
        float b1 = bias[cb + 2 * lc + 1];
        #pragma unroll
        for (int mf = 0; mf < 4; mf++) {
            int row = m0 + core.m_base + mf * 16 + lr;
            float v0 = f_tf32(core.acc[mf][nf][0] + b0);
            float v1 = f_tf32(core.acc[mf][nf][1] + b1);
            float v2 = f_tf32(core.acc[mf][nf][2] + b0);
            float v3 = f_tf32(core.acc[mf][nf][3] + b1);
            if (mat == 0) {
                int colb = ncol0 + cb;
                q[(size_t)row * GN + colb + p0]       = v0;
                q[(size_t)row * GN + colb + p1]       = v1;
                q[(size_t)(row + 8) * GN + colb + p0] = v2;
                q[(size_t)(row + 8) * GN + colb + p1] = v3;
            } else {
                int c0 = ncol0 + cb + 2 * lc;       // logical d col, even
                int n_ = row >> 11;
                int yl = row & (SEQ - 1);
                int hh = c0 >> 6, dh = c0 & 63;
                size_t t0 = (size_t)(n_ * NH + hh) * (SEQ * HD)
                          + (size_t)(yl >> 6) * 4096;
                int y0_ = yl & 63, y1_ = y0_ + 8;   // row,row+8 same 64-tile
                if (mat == 1) {
                    k[t0 + kfrag_idx(y0_, dh)]     = v0;
                    k[t0 + kfrag_idx(y0_, dh + 1)] = v1;
                    k[t0 + kfrag_idx(y1_, dh)]     = v2;
                    k[t0 + kfrag_idx(y1_, dh + 1)] = v3;
                } else {
                    v[t0 + vfrag_idx(y0_, dh)]     = v0;
                    v[t0 + vfrag_idx(y0_, dh + 1)] = v1;
                    v[t0 + vfrag_idx(y1_, dh)]     = v2;
                    v[t0 + vfrag_idx(y1_, dh + 1)] = v3;
                }
            }
        }
    }
}

// Output projection: A (z, afrag), W (bfrag). Standard-layout fp32 output.
__global__ __launch_bounds__(256, 2) void gemm_o_kernel(
    const float* __restrict__ A, const float* __restrict__ W,
    const float* __restrict__ bias, float* __restrict__ C)
{
    extern __shared__ float gsm[];
    GemmCore core;
    core.init(threadIdx.x);
    int n0 = blockIdx.x * 128;
    int m0 = blockIdx.y * 128;
    core.run(gsm, gsm + 2 * GTILE,
             A + (size_t)blockIdx.y * 131072,
             W + (size_t)blockIdx.x * 131072);

    int lr = core.lr, lc = core.lc;
    #pragma unroll
    for (int nf = 0; nf < 4; nf++) {
        int col = n0 + core.n_base + nf * 8 + 2 * lc;
        float b0 = bias[col], b1 = bias[col + 1];
        #pragma unroll
        for (int mf = 0; mf < 4; mf++) {
            int row = m0 + core.m_base + mf * 16 + lr;
            *(float2*)&C[(size_t)row * GN + col] =
                make_float2(core.acc[mf][nf][0] + b0, core.acc[mf][nf][1] + b1);
            *(float2*)&C[(size_t)(row + 8) * GN + col] =
                make_float2(core.acc[mf][nf][2] + b0, core.acc[mf][nf][3] + b1);
        }
    }
}

// ---- Flash Attention: fragment-order K/V (LDS.128), Q in regs ----
#define BQ  128
#define BKT 64
#define AST 72
#define KVN 4096
#define ATTN_SMEM ((4*KVN + BQ*AST) * (int)sizeof(float))

__global__ __launch_bounds__(256, 2) void attn_kernel(
    const float* __restrict__ q, const float* __restrict__ k,
    const float* __restrict__ v, float* __restrict__ z)
{
    extern __shared__ float sm[];
    float* Ks = sm;                    // [2][4096] K fragment tiles
    float* Vt = sm + 2 * KVN;          // [2][4096] V fragment tiles
    float* Ps = sm + 4 * KVN;          // [128 r][AST] permuted y (per-warp)

    int xc = (gridDim.x - 1) - blockIdx.x;
    int h  = blockIdx.y;
    int n  = blockIdx.z;
    int x0 = xc * BQ;
    int t    = threadIdx.x;
    int lane = t & 31;
    int wid  = t >> 5;
    int lr = lane >> 2;
    int lc = lane & 3;
    int m_base = wid * 16;
    float* Pw = Ps + m_base * AST;
    int pp0 = pi8(2 * lc), pp1 = pi8(2 * lc + 1);
    int uoff = (lr * 4 + lc) * 4;      // fragment unit offset within region

    const float* qb = q + ((size_t)n * SEQ) * DH + h * HD;
    const float* kh = k + (size_t)(n * NH + h) * (SEQ * HD);   // fragment tiles
    const float* vh = v + (size_t)(n * NH + h) * (SEQ * HD);

    // prologue: tile 0 (flat 16KB copies)
    #pragma unroll
    for (int i = 0; i < 4; i++) {
        int f4 = (t + i * 256) * 4;
        cp_async16(&Ks[f4], &kh[f4]);
        cp_async16(&Vt[f4], &vh[f4]);
    }
    cp_commit();

    float qa[8][4];
    #pragma unroll
    for (int kk = 0; kk < 8; kk++) {
        float2 lo = *(const float2*)&qb[(size_t)(x0 + m_base + lr) * DH + kk * 8 + 2 * lc];
        float2 hi = *(const float2*)&qb[(size_t)(x0 + m_base + lr + 8) * DH + kk * 8 + 2 * lc];
        qa[kk][0] = lo.x * 0.125f; qa[kk][1] = hi.x * 0.125f;
        qa[kk][2] = lo.y * 0.125f; qa[kk][3] = hi.y * 0.125f;
    }

    float m_lo = -INFINITY, m_hi = -INFINITY, l_lo = 0.f, l_hi = 0.f;
    float o[8][4];
    #pragma unroll
    for (int nf = 0; nf < 8; nf++)
        #pragma unroll
        for (int e = 0; e < 4; e++) o[nf][e] = 0.f;

    int yend = x0 + BQ;
    int buf = 0;
    for (int y0 = 0; y0 < yend; y0 += BKT) {
        bool more = (y0 + BKT < yend);
        if (more) {
            float* Kw = &Ks[(buf ^ 1) * KVN];
            float* Vw = &Vt[(buf ^ 1) * KVN];
            const float* kg = kh + (size_t)((y0 + BKT) >> 6) * KVN;
            const float* vg = vh + (size_t)((y0 + BKT) >> 6) * KVN;
            #pragma unroll
            for (int i = 0; i < 4; i++) {
                int f4 = (t + i * 256) * 4;
                cp_async16(&Kw[f4], &kg[f4]);
                cp_async16(&Vw[f4], &vg[f4]);
            }
            cp_commit();
            cp_wait<1>();
        } else {
            cp_wait<0>();
        }
        __syncthreads();

        const float* Kb = &Ks[buf * KVN];
        const float* Vb = &Vt[buf * KVN];

        // ---- S = Q K^T : 32 LDS.128 ----
        float s[8][4];
        #pragma unroll
        for (int nf = 0; nf < 8; nf++)
            #pragma unroll
            for (int e = 0; e < 4; e++) s[nf][e] = 0.f;

        #pragma unroll
        for (int kk = 0; kk < 8; kk++) {
            int U = kk * 128 + uoff;
            #pragma unroll
            for (int np = 0; np < 4; np++) {
                float4 bb = *(const float4*)&Kb[np * 1024 + U];
                float be[2] = {bb.x, bb.y};
                float bo_[2] = {bb.z, bb.w};
                mma_tf32(s[2 * np],     qa[kk], be);
                mma_tf32(s[2 * np + 1], qa[kk], bo_);
            }
        }

        if (y0 + BKT - 1 > x0) {
            int r_lo = x0 + m_base + lr;
            #pragma unroll
            for (int nf = 0; nf < 8; nf++) {
                int c = y0 + nf * 8 + 2 * lc;
                if (c     > r_lo) s[nf][0] = -INFINITY;
                if (c + 1 > r_lo) s[nf][1] = -INFINITY;
                if (c     > r_lo + 8) s[nf][2] = -INFINITY;
                if (c + 1 > r_lo + 8) s[nf][3] = -INFINITY;
            }
        }

        float mt_lo = -INFINITY, mt_hi = -INFINITY;
        #pragma unroll
        for (int nf = 0; nf < 8; nf++) {
            mt_lo = fmaxf(mt_lo, fmaxf(s[nf][0], s[nf][1]));
            mt_hi = fmaxf(mt_hi, fmaxf(s[nf][2], s[nf][3]));
        }
        #pragma unroll
        for (int off = 1; off <= 2; off <<= 1) {
            mt_lo = fmaxf(mt_lo, __shfl_xor_sync(0xffffffffu, mt_lo, off));
            mt_hi = fmaxf(mt_hi, __shfl_xor_sync(0xffffffffu, mt_hi, off));
        }
        float mn_lo = fmaxf(m_lo, mt_lo);
        float mn_hi = fmaxf(m_hi, mt_hi);
        float al_lo = __expf(m_lo - mn_lo);
        float al_hi = __expf(m_hi - mn_hi);
        m_lo = mn_lo; m_hi = mn_hi;

        float rs_lo = 0.f, rs_hi = 0.f;
        #pragma unroll
        for (int nf = 0; nf < 8; nf++) {
            s[nf][0] = __expf(s[nf][0] - mn_lo);
            s[nf][1] = __expf(s[nf][1] - mn_lo);
            s[nf][2] = __expf(s[nf][2] - mn_hi);
            s[nf][3] = __expf(s[nf][3] - mn_hi);
            rs_lo += s[nf][0] + s[nf][1];
            rs_hi += s[nf][2] + s[nf][3];
        }
        #pragma unroll
        for (int off = 1; off <= 2; off <<= 1) {
            rs_lo += __shfl_xor_sync(0xffffffffu, rs_lo, off);
            rs_hi += __shfl_xor_sync(0xffffffffu, rs_hi, off);
        }
        l_lo = l_lo * al_lo + rs_lo;
        l_hi = l_hi * al_hi + rs_hi;
        #pragma unroll
        for (int nf = 0; nf < 8; nf++) {
            o[nf][0] *= al_lo; o[nf][1] *= al_lo;
            o[nf][2] *= al_hi; o[nf][3] *= al_hi;
        }

        #pragma unroll
        for (int nf = 0; nf < 8; nf++) {
            int q0 = nf * 8 + pp0;
            int q1 = nf * 8 + pp1;
            Pw[lr * AST + q0]       = f_tf32(s[nf][0]);
            Pw[lr * AST + q1]       = f_tf32(s[nf][1]);
            Pw[(lr + 8) * AST + q0] = f_tf32(s[nf][2]);
            Pw[(lr + 8) * AST + q1] = f_tf32(s[nf][3]);
        }
        __syncwarp();

        // ---- O += P V : P LDS.64 pairs + V 32 LDS.128 ----
        #pragma unroll
        for (int kk = 0; kk < 8; kk++) {
            int kb8 = kk * 8 + 2 * lc;
            float2 plo = *(const float2*)&Pw[lr * AST + kb8];
            float2 phi = *(const float2*)&Pw[(lr + 8) * AST + kb8];
            float a[4] = {plo.x, phi.x, plo.y, phi.y};
            int U = kk * 128 + uoff;
            #pragma unroll
            for (int np = 0; np < 4; np++) {
                float4 vv = *(const float4*)&Vb[np * 1024 + U];
                float be[2] = {vv.x, vv.y};
                float bo_[2] = {vv.z, vv.w};
                mma_tf32(o[2 * np],     a, be);
                mma_tf32(o[2 * np + 1], a, bo_);
            }
        }
        __syncwarp();
        __syncthreads();
        buf ^= 1;
    }

    // normalize + store z in A-FRAGMENT order for o-proj
    float inv_lo = 1.0f / l_lo;
    float inv_hi = 1.0f / l_hi;
    int grow = (int)((size_t)n * SEQ) + x0 + m_base + lr;
    #pragma unroll
    for (int nf = 0; nf < 8; nf++) {
        int d0 = h * HD + nf * 8 + 2 * lc;
        z[afrag_idx(grow, d0)]         = f_tf32(o[nf][0] * inv_lo);
        z[afrag_idx(grow, d0 + 1)]     = f_tf32(o[nf][1] * inv_lo);
        z[afrag_idx(grow + 8, d0)]     = f_tf32(o[nf][2] * inv_hi);
        z[afrag_idx(grow + 8, d0 + 1)] = f_tf32(o[nf][3] * inv_hi);
    }
}

// ------------------------------ launcher --------------------------------------
extern "C" void kernel_launch(void* const* d_in, const int* in_sizes, int n_in,
                              void* d_out, int out_size)
{
    const float* x     = (const float*)d_in[0];
    const float* Wq    = (const float*)d_in[1];
    const float* bq    = (const float*)d_in[2];
    const float* Wk    = (const float*)d_in[3];
    const float* bk    = (const float*)d_in[4];
    const float* Wv    = (const float*)d_in[5];
    const float* bv    = (const float*)d_in[6];
    const float* Wo    = (const float*)d_in[7];
    const float* bo    = (const float*)d_in[8];
    const float* gamma = (const float*)d_in[9];
    const float* beta  = (const float*)d_in[10];
    float* out = (float*)d_out;

    float *xn, *qp, *kp, *vp, *zp, *wt, *bqkv;
    cudaGetSymbolAddress((void**)&xn, g_xn);
    cudaGetSymbolAddress((void**)&qp, g_q);
    cudaGetSymbolAddress((void**)&kp, g_k);
    cudaGetSymbolAddress((void**)&vp, g_v);
    cudaGetSymbolAddress((void**)&zp, g_z);
    cudaGetSymbolAddress((void**)&wt, g_wt);
    cudaGetSymbolAddress((void**)&bqkv, g_bqkv);
    float* wqkv = wt;
    float* wo   = wt + 3 * DH * DH;

    cudaFuncSetAttribute(gemm_qkv_kernel,
                         cudaFuncAttributeMaxDynamicSharedMemorySize, GEMM_SMEM);
    cudaFuncSetAttribute(gemm_o_kernel,
                         cudaFuncAttributeMaxDynamicSharedMemorySize, GEMM_SMEM);
    cudaFuncSetAttribute(attn_kernel,
                         cudaFuncAttributeMaxDynamicSharedMemorySize, ATTN_SMEM);

    dim3 wgrid(DH * DH / 1024, 4);
    wcvt_kernel<<<wgrid, 256>>>(Wq, Wk, Wv, Wo, wt);
    bpack_kernel<<<DH / 256, 256>>>(bq, bk, bv, bqkv);

    ln_kernel<<<MROWS / 8, 256>>>(x, gamma, beta, xn);

    dim3 qkvgrid(3 * GN / 128, GM / 128);
    gemm_qkv_kernel<<<qkvgrid, 256, GEMM_SMEM>>>(xn, wqkv, bqkv, qp, kp, vp);

    dim3 agrid(SEQ / BQ, NH, NB);
    attn_kernel<<<agrid, 256, ATTN_SMEM>>>(qp, kp, vp, zp);

    dim3 ogrid(GN / 128, GM / 128);
    gemm_o_kernel<<<ogrid, 256, GEMM_SMEM>>>(zp, wo, bo, out);
}

// round 15
// speedup vs baseline: 1.1260x; 1.0393x over previous
#include <cuda_runtime.h>
#include <cuda_bf16.h>
#include <math.h>
#include <stdint.h>

#define NB   4
#define SEQ  2048
#define DH   1024
#define NH   16
#define HD   64
#define MROWS (NB*SEQ)
#define GM MROWS
#define GN DH
#define GK DH

__device__ float g_xn[MROWS * DH];      // A-fragment order
__device__ float g_q [MROWS * DH];      // permuted cols (pi8)
__device__ float g_k [MROWS * DH];      // K-fragment tiles [NB][NH][SEQ/64][4096]
__device__ float g_v [MROWS * DH];      // V-fragment tiles [NB][NH][SEQ/64][4096]
__device__ float g_z [MROWS * DH];      // A-fragment order
__device__ float g_wt[4][DH * DH];      // tf32, B-fragment order
__device__ float g_bqkv[3 * DH];

#define QSC 0.18033688011112042f        // 0.125 * log2(e)

__device__ __forceinline__ int pi8(int j) { return ((j & 3) << 1) | (j >> 2); }

__device__ __forceinline__ float f_tf32(float x) {
    uint32_t r;
    asm("cvt.rna.tf32.f32 %0, %1;" : "=r"(r) : "f"(x));
    return __uint_as_float(r);
}

__device__ __forceinline__ float ex2f(float x) {
    float r;
    asm("ex2.approx.f32 %0, %1;" : "=f"(r) : "f"(x));
    return r;
}

__device__ __forceinline__ void mma_tf32(float* c, const float* a, const float* b) {
    asm volatile(
        "mma.sync.aligned.m16n8k8.row.col.f32.tf32.tf32.f32 "
        "{%0,%1,%2,%3}, {%4,%5,%6,%7}, {%8,%9}, {%0,%1,%2,%3};\n"
        : "+f"(c[0]), "+f"(c[1]), "+f"(c[2]), "+f"(c[3])
        : "r"(__float_as_uint(a[0])), "r"(__float_as_uint(a[1])),
          "r"(__float_as_uint(a[2])), "r"(__float_as_uint(a[3])),
          "r"(__float_as_uint(b[0])), "r"(__float_as_uint(b[1])));
}

__device__ __forceinline__ void cp_async16(void* smem, const void* gmem) {
    uint32_t s = (uint32_t)__cvta_generic_to_shared(smem);
    asm volatile("cp.async.cg.shared.global [%0], [%1], 16;" :: "r"(s), "l"(gmem));
}
__device__ __forceinline__ void cp_commit() { asm volatile("cp.async.commit_group;"); }
template<int N>
__device__ __forceinline__ void cp_wait() {
    asm volatile("cp.async.wait_group %0;" :: "n"(N));
}

// A-fragment index: unit {A[r][klo],A[r+8][klo],A[r][khi],A[r+8][khi]}
__device__ __forceinline__ size_t afrag_idx(int r, int k) {
    int m128 = r >> 7, rl = r & 127;
    int wm = rl >> 6, mf = (rl >> 4) & 3, er = (rl >> 3) & 1, lr = rl & 7;
    int kt = k >> 5, kk = (k >> 3) & 3, ek = (k >> 2) & 1, lc = k & 3;
    return (size_t)m128 * 131072 + kt * 4096
         + (((((kk * 2 + wm) * 4 + mf) * 8 + lr) * 4 + lc) << 2) + er + 2 * ek;
}

// attention K tile (64y x 64d -> 4096): B-fragment units, nf-paired regions
__device__ __forceinline__ int kfrag_idx(int yl, int dh) {
    int kk = dh >> 3, lcA = dh & 3, eA = (dh >> 2) & 1;
    int lrA = yl & 7, nfA = yl >> 3;
    return (nfA >> 1) * 1024 + (kk * 32 + lrA * 4 + lcA) * 4 + (nfA & 1) * 2 + eA;
}
// attention V tile: k-dim = y, n-dim = d
__device__ __forceinline__ int vfrag_idx(int yl, int dh) {
    int kk = yl >> 3, lcA = yl & 3, eA = (yl >> 2) & 1;
    int lrA = dh & 7, nfA = dh >> 3;
    return (nfA >> 1) * 1024 + (kk * 32 + lrA * 4 + lcA) * 4 + (nfA & 1) * 2 + eA;
}

// ---- weight cvt: tf32 + B-fragment order ----
__global__ __launch_bounds__(256) void wcvt_kernel(
    const float* __restrict__ w0, const float* __restrict__ w1,
    const float* __restrict__ w2, const float* __restrict__ w3,
    float* __restrict__ dst)
{
    const float* srcs[4] = {w0, w1, w2, w3};
    const float* src = srcs[blockIdx.y];
    float* d = dst + (size_t)blockIdx.y * DH * DH;
    int i = (blockIdx.x * 256 + threadIdx.x) * 4;
    int ncol = i >> 10, k = i & 1023;
    float4 v = *(const float4*)&src[i];

    int n128 = ncol >> 7, nloc = ncol & 127;
    int wn = nloc >> 5, nf = (nloc >> 3) & 3, lr = nloc & 7;
    int kt = k >> 5, kk = (k >> 3) & 3, ek = (k >> 2) & 1;
    size_t base = (size_t)n128 * 131072 + kt * 4096 + (nf >> 1) * 2048
                + (nf & 1) * 2 + ek;
    int U0 = ((kk * 4 + wn) * 8 + lr) * 4;
    d[base + (size_t)(U0 + 0) * 4] = f_tf32(v.x);
    d[base + (size_t)(U0 + 1) * 4] = f_tf32(v.y);
    d[base + (size_t)(U0 + 2) * 4] = f_tf32(v.z);
    d[base + (size_t)(U0 + 3) * 4] = f_tf32(v.w);
}

__global__ __launch_bounds__(256) void bpack_kernel(
    const float* __restrict__ b0, const float* __restrict__ b1,
    const float* __restrict__ b2, float* __restrict__ dst)
{
    int i = blockIdx.x * 256 + threadIdx.x;
    dst[i] = b0[i]; dst[i + DH] = b1[i]; dst[i + 2 * DH] = b2[i];
}

// ---- LayerNorm: warp/row, tf32, A-fragment out ----
__global__ __launch_bounds__(256) void ln_kernel(
    const float* __restrict__ x, const float* __restrict__ gamma,
    const float* __restrict__ beta, float* __restrict__ xn)
{
    int warp = threadIdx.x >> 5, lane = threadIdx.x & 31;
    int row = blockIdx.x * 8 + warp;
    const float* xr = x + (size_t)row * DH;

    float4 v[8];
    float s = 0.f, sq = 0.f;
    #pragma unroll
    for (int j = 0; j < 8; j++) {
        v[j] = *(const float4*)&xr[(j * 32 + lane) * 4];
        s  += v[j].x + v[j].y + v[j].z + v[j].w;
        sq += v[j].x * v[j].x + v[j].y * v[j].y
            + v[j].z * v[j].z + v[j].w * v[j].w;
    }
    #pragma unroll
    for (int off = 16; off > 0; off >>= 1) {
        s  += __shfl_xor_sync(0xffffffffu, s,  off);
        sq += __shfl_xor_sync(0xffffffffu, sq, off);
    }
    float mu  = s * (1.0f / DH);
    float var = sq * (1.0f / DH) - mu * mu;
    float inv = rsqrtf(var + 1e-5f);

    #pragma unroll
    for (int j = 0; j < 8; j++) {
        int c = (j * 32 + lane) * 4;
        float4 g = *(const float4*)&gamma[c];
        float4 b = *(const float4*)&beta[c];
        size_t i0 = afrag_idx(row, c);
        xn[i0]      = f_tf32((v[j].x - mu) * inv * g.x + b.x);
        xn[i0 + 4]  = f_tf32((v[j].y - mu) * inv * g.y + b.y);
        xn[i0 + 8]  = f_tf32((v[j].z - mu) * inv * g.z + b.z);
        xn[i0 + 12] = f_tf32((v[j].w - mu) * inv * g.w + b.w);
    }
}

// ---- GEMM core: fragment-order operands, 3-stage cp.async pipeline ----
#define GTILE 4096
#define GEMM_SMEM (6 * GTILE * (int)sizeof(float))

struct GemmCore {
    float acc[4][4][4];
    int t, lr, lc, wm, wn, m_base, n_base;

    __device__ __forceinline__ void init(int tid) {
        t = tid;
        int lane = t & 31, wid = t >> 5;
        lr = lane >> 2; lc = lane & 3;
        wm = wid & 1; wn = wid >> 1;
        m_base = wm * 64; n_base = wn * 32;
        #pragma unroll
        for (int i = 0; i < 4; i++)
            #pragma unroll
            for (int j = 0; j < 4; j++)
                #pragma unroll
                for (int e = 0; e < 4; e++) acc[i][j][e] = 0.f;
    }

    __device__ __forceinline__ void issue_tile(
        float* As, float* Bs, const float* At, const float* Bt, int kt, int slot)
    {
        float* Aw = &As[slot * GTILE];
        float* Bw = &Bs[slot * GTILE];
        const float* Ag = At + (size_t)kt * GTILE;
        const float* Bg = Bt + (size_t)kt * GTILE;
        #pragma unroll
        for (int i = 0; i < 4; i++) {
            int f4 = (t + i * 256) * 4;
            cp_async16(&Aw[f4], &Ag[f4]);
            cp_async16(&Bw[f4], &Bg[f4]);
        }
        cp_commit();
    }

    __device__ __forceinline__ void run(
        float* As, float* Bs,
        const float* __restrict__ At, const float* __restrict__ Bt)
    {
        issue_tile(As, Bs, At, Bt, 0, 0);
        issue_tile(As, Bs, At, Bt, 1, 1);

        int cur = 0;
        for (int kt = 0; kt < 32; kt++) {
            if (kt == 31) cp_wait<0>(); else cp_wait<1>();
            __syncthreads();

            if (kt + 2 < 32) {
                int slot = cur + 2; if (slot >= 3) slot -= 3;
                issue_tile(As, Bs, At, Bt, kt + 2, slot);
            }

            const float* Ab = &As[cur * GTILE];
            const float* Bb = &Bs[cur * GTILE];
            #pragma unroll
            for (int kk = 0; kk < 4; kk++) {
                float a[4][4], b[4][2];
                #pragma unroll
                for (int mf = 0; mf < 4; mf++) {
                    float4 av = *(const float4*)
                        &Ab[(((((kk * 2 + wm) * 4 + mf) * 8 + lr) * 4 + lc) << 2)];
                    a[mf][0] = av.x; a[mf][1] = av.y;
                    a[mf][2] = av.z; a[mf][3] = av.w;
                }
                int U = (((kk * 4 + wn) * 8 + lr) * 4 + lc) << 2;
                float4 b01 = *(const float4*)&Bb[U];
                float4 b23 = *(const float4*)&Bb[2048 + U];
                b[0][0] = b01.x; b[0][1] = b01.y;
                b[1][0] = b01.z; b[1][1] = b01.w;
                b[2][0] = b23.x; b[2][1] = b23.y;
                b[3][0] = b23.z; b[3][1] = b23.w;
                #pragma unroll
                for (int mf = 0; mf < 4; mf++)
                    #pragma unroll
                    for (int nf = 0; nf < 4; nf++)
                        mma_tf32(acc[mf][nf], a[mf], b[nf]);
            }
            cur++; if (cur >= 3) cur = 0;
        }
    }
};

// Fused QKV. Writes q permuted-row-major; k,v fragment-ordered head tiles.
__global__ __launch_bounds__(256, 2) void gemm_qkv_kernel(
    const float* __restrict__ A, const float* __restrict__ Wp,
    const float* __restrict__ bp,
    float* __restrict__ q, float* __restrict__ k, float* __restrict__ v)
{
    extern __shared__ float gsm[];
    GemmCore core;
    core.init(threadIdx.x);

    int npack0 = blockIdx.x * 128;
    int m0 = blockIdx.y * 128;
    int mat = npack0 >> 10;
    int ncol0 = npack0 & 1023;

    core.run(gsm, gsm + 3 * GTILE,
             A  + (size_t)blockIdx.y * 131072,
             Wp + (size_t)blockIdx.x * 131072);

    const float* bias = bp + npack0;
    int lr = core.lr, lc = core.lc;
    int p0 = pi8(2 * lc), p1 = pi8(2 * lc + 1);

    #pragma unroll
    for (int nf = 0; nf < 4; nf++) {
        int cb = core.n_base + nf * 8;
        float b0 = bias[cb + 2 * lc];
        float b1 = bias[cb + 2 * lc + 1];
        #pragma unroll
        for (int mf = 0; mf < 4; mf++) {
            int row = m0 + core.m_base + mf * 16 + lr;
            float v0 = f_tf32(core.acc[mf][nf][0] + b0);
            float v1 = f_tf32(core.acc[mf][nf][1] + b1);
            float v2 = f_tf32(core.acc[mf][nf][2] + b0);
            float v3 = f_tf32(core.acc[mf][nf][3] + b1);
            if (mat == 0) {
                int colb = ncol0 + cb;
                q[(size_t)row * GN + colb + p0]       = v0;
                q[(size_t)row * GN + colb + p1]       = v1;
                q[(size_t)(row + 8) * GN + colb + p0] = v2;
                q[(size_t)(row + 8) * GN + colb + p1] = v3;
            } else {
                int c0 = ncol0 + cb + 2 * lc;
                int n_ = row >> 11;
                int yl = row & (SEQ - 1);
                int hh = c0 >> 6, dh = c0 & 63;
                size_t t0 = (size_t)(n_ * NH + hh) * (SEQ * HD)
                          + (size_t)(yl >> 6) * 4096;
                int y0_ = yl & 63, y1_ = y0_ + 8;
                if (mat == 1) {
                    k[t0 + kfrag_idx(y0_, dh)]     = v0;
                    k[t0 + kfrag_idx(y0_, dh + 1)] = v1;
                    k[t0 + kfrag_idx(y1_, dh)]     = v2;
                    k[t0 + kfrag_idx(y1_, dh + 1)] = v3;
                } else {
                    v[t0 + vfrag_idx(y0_, dh)]     = v0;
                    v[t0 + vfrag_idx(y0_, dh + 1)] = v1;
                    v[t0 + vfrag_idx(y1_, dh)]     = v2;
                    v[t0 + vfrag_idx(y1_, dh + 1)] = v3;
                }
            }
        }
    }
}

// Output projection.
__global__ __launch_bounds__(256, 2) void gemm_o_kernel(
    const float* __restrict__ A, const float* __restrict__ W,
    const float* __restrict__ bias, float* __restrict__ C)
{
    extern __shared__ float gsm[];
    GemmCore core;
    core.init(threadIdx.x);
    int n0 = blockIdx.x * 128;
    int m0 = blockIdx.y * 128;
    core.run(gsm, gsm + 3 * GTILE,
             A + (size_t)blockIdx.y * 131072,
             W + (size_t)blockIdx.x * 131072);

    int lr = core.lr, lc = core.lc;
    #pragma unroll
    for (int nf = 0; nf < 4; nf++) {
        int col = n0 + core.n_base + nf * 8 + 2 * lc;
        float b0 = bias[col], b1 = bias[col + 1];
        #pragma unroll
        for (int mf = 0; mf < 4; mf++) {
            int row = m0 + core.m_base + mf * 16 + lr;
            *(float2*)&C[(size_t)row * GN + col] =
                make_float2(core.acc[mf][nf][0] + b0, core.acc[mf][nf][1] + b1);
            *(float2*)&C[(size_t)(row + 8) * GN + col] =
                make_float2(core.acc[mf][nf][2] + b0, core.acc[mf][nf][3] + b1);
        }
    }
}

// ---- Flash Attention: log2-softmax, 1 barrier/tile, frag K/V ----
#define BQ  128
#define BKT 64
#define AST 72
#define KVN 4096
#define ATTN_SMEM ((4*KVN + BQ*AST) * (int)sizeof(float))

__global__ __launch_bounds__(256, 2) void attn_kernel(
    const float* __restrict__ q, const float* __restrict__ k,
    const float* __restrict__ v, float* __restrict__ z)
{
    extern __shared__ float sm[];
    float* Ks = sm;
    float* Vt = sm + 2 * KVN;
    float* Ps = sm + 4 * KVN;

    int xc = (gridDim.x - 1) - blockIdx.x;
    int h  = blockIdx.y;
    int n  = blockIdx.z;
    int x0 = xc * BQ;
    int t    = threadIdx.x;
    int lane = t & 31;
    int wid  = t >> 5;
    int lr = lane >> 2;
    int lc = lane & 3;
    int m_base = wid * 16;
    float* Pw = Ps + m_base * AST;
    int pp0 = pi8(2 * lc), pp1 = pi8(2 * lc + 1);
    int uoff = (lr * 4 + lc) * 4;

    const float* qb = q + ((size_t)n * SEQ) * DH + h * HD;
    const float* kh = k + (size_t)(n * NH + h) * (SEQ * HD);
    const float* vh = v + (size_t)(n * NH + h) * (SEQ * HD);

    // prologue: tile 0 (one group)
    #pragma unroll
    for (int i = 0; i < 4; i++) {
        int f4 = (t + i * 256) * 4;
        cp_async16(&Ks[f4], &kh[f4]);
        cp_async16(&Vt[f4], &vh[f4]);
    }
    cp_commit();

    // Q in registers, scale = 0.125*log2e folded in (log2-domain softmax)
    float qa[8][4];
    #pragma unroll
    for (int kk = 0; kk < 8; kk++) {
        float2 lo = *(const float2*)&qb[(size_t)(x0 + m_base + lr) * DH + kk * 8 + 2 * lc];
        float2 hi = *(const float2*)&qb[(size_t)(x0 + m_base + lr + 8) * DH + kk * 8 + 2 * lc];
        qa[kk][0] = lo.x * QSC; qa[kk][1] = hi.x * QSC;
        qa[kk][2] = lo.y * QSC; qa[kk][3] = hi.y * QSC;
    }

    float m_lo = -INFINITY, m_hi = -INFINITY, l_lo = 0.f, l_hi = 0.f;
    float o[8][4];
    #pragma unroll
    for (int nf = 0; nf < 8; nf++)
        #pragma unroll
        for (int e = 0; e < 4; e++) o[nf][e] = 0.f;

    int yend = x0 + BQ;
    int buf = 0;
    for (int y0 = 0; y0 < yend; y0 += BKT) {
        cp_wait<0>();          // tile i complete (only group outstanding)
        __syncthreads();       // visible to all; prior iter's readers done

        if (y0 + BKT < yend) { // prefetch i+1 into buf^1 (safe after barrier)
            float* Kw = &Ks[(buf ^ 1) * KVN];
            float* Vw = &Vt[(buf ^ 1) * KVN];
            const float* kg = kh + (size_t)((y0 + BKT) >> 6) * KVN;
            const float* vg = vh + (size_t)((y0 + BKT) >> 6) * KVN;
            #pragma unroll
            for (int i = 0; i < 4; i++) {
                int f4 = (t + i * 256) * 4;
                cp_async16(&Kw[f4], &kg[f4]);
                cp_async16(&Vw[f4], &vg[f4]);
            }
            cp_commit();
        }

        const float* Kb = &Ks[buf * KVN];
        const float* Vb = &Vt[buf * KVN];

        // ---- S = Q K^T (log2-scaled) ----
        float s[8][4];
        #pragma unroll
        for (int nf = 0; nf < 8; nf++)
            #pragma unroll
            for (int e = 0; e < 4; e++) s[nf][e] = 0.f;

        #pragma unroll
        for (int kk = 0; kk < 8; kk++) {
            int U = kk * 128 + uoff;
            #pragma unroll
            for (int np = 0; np < 4; np++) {
                float4 bb = *(const float4*)&Kb[np * 1024 + U];
                float be[2] = {bb.x, bb.y};
                float bo_[2] = {bb.z, bb.w};
                mma_tf32(s[2 * np],     qa[kk], be);
                mma_tf32(s[2 * np + 1], qa[kk], bo_);
            }
        }

        if (y0 + BKT - 1 > x0) {
            int r_lo = x0 + m_base + lr;
            #pragma unroll
            for (int nf = 0; nf < 8; nf++) {
                int c = y0 + nf * 8 + 2 * lc;
                if (c     > r_lo) s[nf][0] = -INFINITY;
                if (c + 1 > r_lo) s[nf][1] = -INFINITY;
                if (c     > r_lo + 8) s[nf][2] = -INFINITY;
                if (c + 1 > r_lo + 8) s[nf][3] = -INFINITY;
            }
        }

        // ---- online softmax in log2 domain ----
        float mt_lo = -INFINITY, mt_hi = -INFINITY;
        #pragma unroll
        for (int nf = 0; nf < 8; nf++) {
            mt_lo = fmaxf(mt_lo, fmaxf(s[nf][0], s[nf][1]));
            mt_hi = fmaxf(mt_hi, fmaxf(s[nf][2], s[nf][3]));
        }
        #pragma unroll
        for (int off = 1; off <= 2; off <<= 1) {
            mt_lo = fmaxf(mt_lo, __shfl_xor_sync(0xffffffffu, mt_lo, off));
            mt_hi = fmaxf(mt_hi, __shfl_xor_sync(0xffffffffu, mt_hi, off));
        }
        float mn_lo = fmaxf(m_lo, mt_lo);
        float mn_hi = fmaxf(m_hi, mt_hi);
        float al_lo = ex2f(m_lo - mn_lo);
        float al_hi = ex2f(m_hi - mn_hi);
        m_lo = mn_lo; m_hi = mn_hi;

        float rs_lo = 0.f, rs_hi = 0.f;
        #pragma unroll
        for (int nf = 0; nf < 8; nf++) {
            s[nf][0] = ex2f(s[nf][0] - mn_lo);
            s[nf][1] = ex2f(s[nf][1] - mn_lo);
            s[nf][2] = ex2f(s[nf][2] - mn_hi);
            s[nf][3] = ex2f(s[nf][3] - mn_hi);
            rs_lo += s[nf][0] + s[nf][1];
            rs_hi += s[nf][2] + s[nf][3];
        }
        #pragma unroll
        for (int off = 1; off <= 2; off <<= 1) {
            rs_lo += __shfl_xor_sync(0xffffffffu, rs_lo, off);
            rs_hi += __shfl_xor_sync(0xffffffffu, rs_hi, off);
        }
        l_lo = l_lo * al_lo + rs_lo;
        l_hi = l_hi * al_hi + rs_hi;
        #pragma unroll
        for (int nf = 0; nf < 8; nf++) {
            o[nf][0] *= al_lo; o[nf][1] *= al_lo;
            o[nf][2] *= al_hi; o[nf][3] *= al_hi;
        }

        // ---- stage P raw fp32 (tf32 mma truncates; P in [0,1]) ----
        #pragma unroll
        for (int nf = 0; nf < 8; nf++) {
            int q0 = nf * 8 + pp0;
            int q1 = nf * 8 + pp1;
            Pw[lr * AST + q0]       = s[nf][0];
            Pw[lr * AST + q1]       = s[nf][1];
            Pw[(lr + 8) * AST + q0] = s[nf][2];
            Pw[(lr + 8) * AST + q1] = s[nf][3];
        }
        __syncwarp();

        // ---- O += P V ----
        #pragma unroll
        for (int kk = 0; kk < 8; kk++) {
            int kb8 = kk * 8 + 2 * lc;
            float2 plo = *(const float2*)&Pw[lr * AST + kb8];
            float2 phi = *(const float2*)&Pw[(lr + 8) * AST + kb8];
            float a[4] = {plo.x, phi.x, plo.y, phi.y};
            int U = kk * 128 + uoff;
            #pragma unroll
            for (int np = 0; np < 4; np++) {
                float4 vv = *(const float4*)&Vb[np * 1024 + U];
                float be[2] = {vv.x, vv.y};
                float bo_[2] = {vv.z, vv.w};
                mma_tf32(o[2 * np],     a, be);
                mma_tf32(o[2 * np + 1], a, bo_);
            }
        }
        buf ^= 1;   // next iter's top barrier orders Pw/buf reuse
    }

    // normalize + store z in A-fragment order
    float inv_lo = 1.0f / l_lo;
    float inv_hi = 1.0f / l_hi;
    int grow = (int)((size_t)n * SEQ) + x0 + m_base + lr;
    #pragma unroll
    for (int nf = 0; nf < 8; nf++) {
        int d0 = h * HD + nf * 8 + 2 * lc;
        z[afrag_idx(grow, d0)]         = f_tf32(o[nf][0] * inv_lo);
        z[afrag_idx(grow, d0 + 1)]     = f_tf32(o[nf][1] * inv_lo);
        z[afrag_idx(grow + 8, d0)]     = f_tf32(o[nf][2] * inv_hi);
        z[afrag_idx(grow + 8, d0 + 1)] = f_tf32(o[nf][3] * inv_hi);
    }
}

// ------------------------------ launcher --------------------------------------
extern "C" void kernel_launch(void* const* d_in, const int* in_sizes, int n_in,
                              void* d_out, int out_size)
{
    const float* x     = (const float*)d_in[0];
    const float* Wq    = (const float*)d_in[1];
    const float* bq    = (const float*)d_in[2];
    const float* Wk    = (const float*)d_in[3];
    const float* bk    = (const float*)d_in[4];
    const float* Wv    = (const float*)d_in[5];
    const float* bv    = (const float*)d_in[6];
    const float* Wo    = (const float*)d_in[7];
    const float* bo    = (const float*)d_in[8];
    const float* gamma = (const float*)d_in[9];
    const float* beta  = (const float*)d_in[10];
    float* out = (float*)d_out;

    float *xn, *qp, *kp, *vp, *zp, *wt, *bqkv;
    cudaGetSymbolAddress((void**)&xn, g_xn);
    cudaGetSymbolAddress((void**)&qp, g_q);
    cudaGetSymbolAddress((void**)&kp, g_k);
    cudaGetSymbolAddress((void**)&vp, g_v);
    cudaGetSymbolAddress((void**)&zp, g_z);
    cudaGetSymbolAddress((void**)&wt, g_wt);
    cudaGetSymbolAddress((void**)&bqkv, g_bqkv);
    float* wqkv = wt;
    float* wo   = wt + 3 * DH * DH;

    cudaFuncSetAttribute(gemm_qkv_kernel,
                         cudaFuncAttributeMaxDynamicSharedMemorySize, GEMM_SMEM);
    cudaFuncSetAttribute(gemm_o_kernel,
                         cudaFuncAttributeMaxDynamicSharedMemorySize, GEMM_SMEM);
    cudaFuncSetAttribute(attn_kernel,
                         cudaFuncAttributeMaxDynamicSharedMemorySize, ATTN_SMEM);

    dim3 wgrid(DH * DH / 1024, 4);
    wcvt_kernel<<<wgrid, 256>>>(Wq, Wk, Wv, Wo, wt);
    bpack_kernel<<<DH / 256, 256>>>(bq, bk, bv, bqkv);

    ln_kernel<<<MROWS / 8, 256>>>(x, gamma, beta, xn);

    dim3 qkvgrid(3 * GN / 128, GM / 128);
    gemm_qkv_kernel<<<qkvgrid, 256, GEMM_SMEM>>>(xn, wqkv, bqkv, qp, kp, vp);

    dim3 agrid(SEQ / BQ, NH, NB);
    attn_kernel<<<agrid, 256, ATTN_SMEM>>>(qp, kp, vp, zp);

    dim3 ogrid(GN / 128, GM / 128);
    gemm_o_kernel<<<ogrid, 256, GEMM_SMEM>>>(zp, wo, bo, out);
}